// round 1
// baseline (speedup 1.0000x reference)
#include <cuda_runtime.h>

// Problem constants
#define Bsz    2
#define Nseq   2048
#define Dmodel 1024
#define Hh     16
#define DKh    64
#define Mrows  4096   // Bsz*Nseq
#define SCALE  0.125f // DKh^-0.5

// Scratch (static device allocations are allowed; cudaMalloc is not)
__device__ float g_Q[Mrows * Dmodel];
__device__ float g_K[Mrows * Dmodel];
__device__ float g_V[Mrows * Dmodel];
__device__ float g_C[Mrows * Dmodel];

// ---------------------------------------------------------------------------
// GEMM: C[M,1024] = X[M,1024] @ W[1024,1024]^T + bias   (both row-major, NT)
// Tile 128x128x16, 256 threads, 8x8 per-thread register block.
// ---------------------------------------------------------------------------
#define BM 128
#define BN 128
#define BK 16

__device__ __forceinline__ void gemm_body(const float* __restrict__ X,
                                          const float* __restrict__ W,
                                          const float* __restrict__ bias,
                                          float* __restrict__ C)
{
    __shared__ __align__(16) float As[BK][BM + 4];
    __shared__ __align__(16) float Bs[BK][BN + 4];

    const int tid = threadIdx.x;       // 0..255
    const int tx  = tid & 15;          // 0..15 -> n
    const int ty  = tid >> 4;          // 0..15 -> m
    const int m0  = blockIdx.y * BM;
    const int n0  = blockIdx.x * BN;
    const int lr  = tid >> 2;          // 0..63
    const int lc  = (tid & 3) << 2;    // 0,4,8,12

    float acc[8][8];
#pragma unroll
    for (int r = 0; r < 8; r++)
#pragma unroll
        for (int c = 0; c < 8; c++) acc[r][c] = 0.0f;

    for (int k0 = 0; k0 < Dmodel; k0 += BK) {
        float4 a0 = *(const float4*)(X + (size_t)(m0 + lr) * Dmodel + k0 + lc);
        float4 a1 = *(const float4*)(X + (size_t)(m0 + lr + 64) * Dmodel + k0 + lc);
        float4 b0 = *(const float4*)(W + (size_t)(n0 + lr) * Dmodel + k0 + lc);
        float4 b1 = *(const float4*)(W + (size_t)(n0 + lr + 64) * Dmodel + k0 + lc);

        As[lc + 0][lr] = a0.x; As[lc + 1][lr] = a0.y;
        As[lc + 2][lr] = a0.z; As[lc + 3][lr] = a0.w;
        As[lc + 0][lr + 64] = a1.x; As[lc + 1][lr + 64] = a1.y;
        As[lc + 2][lr + 64] = a1.z; As[lc + 3][lr + 64] = a1.w;

        Bs[lc + 0][lr] = b0.x; Bs[lc + 1][lr] = b0.y;
        Bs[lc + 2][lr] = b0.z; Bs[lc + 3][lr] = b0.w;
        Bs[lc + 0][lr + 64] = b1.x; Bs[lc + 1][lr + 64] = b1.y;
        Bs[lc + 2][lr + 64] = b1.z; Bs[lc + 3][lr + 64] = b1.w;

        __syncthreads();

#pragma unroll
        for (int kk = 0; kk < BK; kk++) {
            float a[8], b[8];
            *(float4*)&a[0] = *(const float4*)&As[kk][ty * 8];
            *(float4*)&a[4] = *(const float4*)&As[kk][ty * 8 + 4];
            *(float4*)&b[0] = *(const float4*)&Bs[kk][tx * 8];
            *(float4*)&b[4] = *(const float4*)&Bs[kk][tx * 8 + 4];
#pragma unroll
            for (int r = 0; r < 8; r++)
#pragma unroll
                for (int c = 0; c < 8; c++)
                    acc[r][c] = fmaf(a[r], b[c], acc[r][c]);
        }
        __syncthreads();
    }

#pragma unroll
    for (int r = 0; r < 8; r++) {
        const int m = m0 + ty * 8 + r;
#pragma unroll
        for (int c = 0; c < 8; c += 4) {
            const int n = n0 + tx * 8 + c;
            float4 o;
            o.x = acc[r][c + 0] + bias[n + 0];
            o.y = acc[r][c + 1] + bias[n + 1];
            o.z = acc[r][c + 2] + bias[n + 2];
            o.w = acc[r][c + 3] + bias[n + 3];
            *(float4*)(C + (size_t)m * Dmodel + n) = o;
        }
    }
}

__global__ __launch_bounds__(256) void qkv_gemm(
    const float* __restrict__ q, const float* __restrict__ k, const float* __restrict__ v,
    const float* __restrict__ Wq, const float* __restrict__ bq,
    const float* __restrict__ Wk, const float* __restrict__ bk,
    const float* __restrict__ Wv, const float* __restrict__ bv)
{
    const int which = blockIdx.z;
    const float* X    = (which == 0) ? q  : (which == 1) ? k  : v;
    const float* W    = (which == 0) ? Wq : (which == 1) ? Wk : Wv;
    const float* bias = (which == 0) ? bq : (which == 1) ? bk : bv;
    float* C          = (which == 0) ? g_Q : (which == 1) ? g_K : g_V;
    gemm_body(X, W, bias, C);
}

__global__ __launch_bounds__(256) void out_gemm(const float* __restrict__ Wo,
                                                const float* __restrict__ bo,
                                                float* __restrict__ out)
{
    gemm_body(g_C, Wo, bo, out);
}

// ---------------------------------------------------------------------------
// Flash attention, fp32. Tiles: 64 query rows x 64 key rows, DK=64.
// 256 threads (16x16), each thread owns a 4x4 block of S/P and of O.
// Online softmax; row stats reduced across tx via shfl (16-lane groups).
// smem: Qst[d][m], Kst[d][n], Vs[j][d], Pst[j][m], stride 68 floats each.
// ---------------------------------------------------------------------------
#define FSTRIDE 68
#define FLASH_SMEM (4 * 64 * FSTRIDE * (int)sizeof(float))   // 69632 B

__global__ __launch_bounds__(256) void flash_attn()
{
    extern __shared__ __align__(16) float sm[];
    float* Qst = sm;                     // [64][68]  (d-major)
    float* Kst = sm + 64 * FSTRIDE;      // [64][68]  (d-major)
    float* Vs  = sm + 2 * 64 * FSTRIDE;  // [64][68]  (j-major, natural)
    float* Pst = sm + 3 * 64 * FSTRIDE;  // [64][68]  (j-major)

    const int tid = threadIdx.x;
    const int tx  = tid & 15;            // column group (keys / head-dim)
    const int ty  = tid >> 4;            // row group (queries)
    const int bh  = blockIdx.y;
    const int b   = bh >> 4;
    const int h   = bh & 15;
    const int q0  = blockIdx.x * 64;

    const float* Qb = g_Q + (size_t)b * Nseq * Dmodel + h * DKh;
    const float* Kb = g_K + (size_t)b * Nseq * Dmodel + h * DKh;
    const float* Vb = g_V + (size_t)b * Nseq * Dmodel + h * DKh;

    const int lr  = tid >> 2;            // 0..63
    const int lc0 = (tid & 3) << 4;      // 0,16,32,48

    // Load Q tile transposed (d-major)
#pragma unroll
    for (int i = 0; i < 4; i++) {
        const int d = lc0 + i * 4;
        float4 qv = *(const float4*)(Qb + (size_t)(q0 + lr) * Dmodel + d);
        Qst[(d + 0) * FSTRIDE + lr] = qv.x;
        Qst[(d + 1) * FSTRIDE + lr] = qv.y;
        Qst[(d + 2) * FSTRIDE + lr] = qv.z;
        Qst[(d + 3) * FSTRIDE + lr] = qv.w;
    }

    float o[4][4];
#pragma unroll
    for (int r = 0; r < 4; r++)
#pragma unroll
        for (int c = 0; c < 4; c++) o[r][c] = 0.0f;
    float mrow[4] = {-1e30f, -1e30f, -1e30f, -1e30f};
    float lrow[4] = {0.0f, 0.0f, 0.0f, 0.0f};

    for (int j0 = 0; j0 < Nseq; j0 += 64) {
        // Load K (transposed, d-major) and V (natural, j-major)
#pragma unroll
        for (int i = 0; i < 4; i++) {
            const int d = lc0 + i * 4;
            float4 kv = *(const float4*)(Kb + (size_t)(j0 + lr) * Dmodel + d);
            Kst[(d + 0) * FSTRIDE + lr] = kv.x;
            Kst[(d + 1) * FSTRIDE + lr] = kv.y;
            Kst[(d + 2) * FSTRIDE + lr] = kv.z;
            Kst[(d + 3) * FSTRIDE + lr] = kv.w;
            float4 vv = *(const float4*)(Vb + (size_t)(j0 + lr) * Dmodel + d);
            *(float4*)&Vs[lr * FSTRIDE + d] = vv;
        }
        __syncthreads();   // Q (first iter), K, V visible

        // S = Q @ K^T (4x4 per thread)
        float s[4][4];
#pragma unroll
        for (int r = 0; r < 4; r++)
#pragma unroll
            for (int c = 0; c < 4; c++) s[r][c] = 0.0f;
#pragma unroll 8
        for (int d = 0; d < 64; d++) {
            float4 a  = *(const float4*)&Qst[d * FSTRIDE + ty * 4];
            float4 bb = *(const float4*)&Kst[d * FSTRIDE + tx * 4];
            const float av[4] = {a.x, a.y, a.z, a.w};
            const float bv[4] = {bb.x, bb.y, bb.z, bb.w};
#pragma unroll
            for (int r = 0; r < 4; r++)
#pragma unroll
                for (int c = 0; c < 4; c++)
                    s[r][c] = fmaf(av[r], bv[c], s[r][c]);
        }

        // Online softmax update per row (rows owned by ty, replicated over tx)
#pragma unroll
        for (int r = 0; r < 4; r++) {
            float s0 = s[r][0] * SCALE, s1 = s[r][1] * SCALE;
            float s2 = s[r][2] * SCALE, s3 = s[r][3] * SCALE;
            float mx = fmaxf(fmaxf(s0, s1), fmaxf(s2, s3));
#pragma unroll
            for (int off = 1; off < 16; off <<= 1)
                mx = fmaxf(mx, __shfl_xor_sync(0xffffffffu, mx, off));
            const float mnew = fmaxf(mrow[r], mx);
            const float p0 = __expf(s0 - mnew);
            const float p1 = __expf(s1 - mnew);
            const float p2 = __expf(s2 - mnew);
            const float p3 = __expf(s3 - mnew);
            float rs = p0 + p1 + p2 + p3;
#pragma unroll
            for (int off = 1; off < 16; off <<= 1)
                rs += __shfl_xor_sync(0xffffffffu, rs, off);
            const float alpha = __expf(mrow[r] - mnew);
            lrow[r] = lrow[r] * alpha + rs;
            mrow[r] = mnew;
            o[r][0] *= alpha; o[r][1] *= alpha;
            o[r][2] *= alpha; o[r][3] *= alpha;
            // Store P transposed: Pst[key j][query m]
            Pst[(tx * 4 + 0) * FSTRIDE + ty * 4 + r] = p0;
            Pst[(tx * 4 + 1) * FSTRIDE + ty * 4 + r] = p1;
            Pst[(tx * 4 + 2) * FSTRIDE + ty * 4 + r] = p2;
            Pst[(tx * 4 + 3) * FSTRIDE + ty * 4 + r] = p3;
        }
        __syncthreads();   // P visible, S-gemm done reading Kst

        // O += P @ V
#pragma unroll 8
        for (int j = 0; j < 64; j++) {
            float4 p  = *(const float4*)&Pst[j * FSTRIDE + ty * 4];
            float4 vv = *(const float4*)&Vs[j * FSTRIDE + tx * 4];
            const float pv[4] = {p.x, p.y, p.z, p.w};
            const float vvv[4] = {vv.x, vv.y, vv.z, vv.w};
#pragma unroll
            for (int r = 0; r < 4; r++)
#pragma unroll
                for (int c = 0; c < 4; c++)
                    o[r][c] = fmaf(pv[r], vvv[c], o[r][c]);
        }
        __syncthreads();   // done with Kst/Vs/Pst before next tile load
    }

    // Epilogue: normalize and write back to [b, n, h*64 + d] layout
    float* Cb = g_C + (size_t)b * Nseq * Dmodel + h * DKh;
#pragma unroll
    for (int r = 0; r < 4; r++) {
        const float inv = 1.0f / lrow[r];
        float4 ov;
        ov.x = o[r][0] * inv; ov.y = o[r][1] * inv;
        ov.z = o[r][2] * inv; ov.w = o[r][3] * inv;
        *(float4*)(Cb + (size_t)(q0 + ty * 4 + r) * Dmodel + tx * 4) = ov;
    }
}

// ---------------------------------------------------------------------------
extern "C" void kernel_launch(void* const* d_in, const int* in_sizes, int n_in,
                              void* d_out, int out_size)
{
    const float* q  = (const float*)d_in[0];
    const float* k  = (const float*)d_in[1];
    const float* v  = (const float*)d_in[2];
    const float* Wq = (const float*)d_in[3];
    const float* bq = (const float*)d_in[4];
    const float* Wk = (const float*)d_in[5];
    const float* bk = (const float*)d_in[6];
    const float* Wv = (const float*)d_in[7];
    const float* bv = (const float*)d_in[8];
    const float* Wo = (const float*)d_in[9];
    const float* bo = (const float*)d_in[10];
    float* out = (float*)d_out;

    cudaFuncSetAttribute(flash_attn, cudaFuncAttributeMaxDynamicSharedMemorySize,
                         FLASH_SMEM);

    dim3 gqkv(Dmodel / BN, Mrows / BM, 3);   // 8 x 32 x 3
    qkv_gemm<<<gqkv, 256>>>(q, k, v, Wq, bq, Wk, bk, Wv, bv);

    dim3 gf(Nseq / 64, Bsz * Hh);            // 32 x 32
    flash_attn<<<gf, 256, FLASH_SMEM>>>();

    dim3 go(Dmodel / BN, Mrows / BM);        // 8 x 32
    out_gemm<<<go, 256>>>(Wo, bo, out);
}

// round 2
// speedup vs baseline: 1.0039x; 1.0039x over previous
#include <cuda_runtime.h>

// Problem constants
#define Bsz    2
#define Nseq   2048
#define Dmodel 1024
#define Hh     16
#define DKh    64
#define Mrows  4096   // Bsz*Nseq
#define SCALE  0.125f // DKh^-0.5

typedef unsigned long long ull;

// ---- packed fp32x2 helpers (Blackwell fp32x2 pipe; ptxas never auto-fuses) ----
__device__ __forceinline__ ull f2pack(float lo, float hi) {
    ull r; asm("mov.b64 %0,{%1,%2};" : "=l"(r) : "f"(lo), "f"(hi)); return r;
}
__device__ __forceinline__ void f2unpack(ull p, float& lo, float& hi) {
    asm("mov.b64 {%0,%1},%2;" : "=f"(lo), "=f"(hi) : "l"(p));
}
__device__ __forceinline__ ull ffma2(ull a, ull b, ull c) {
    ull d; asm("fma.rn.f32x2 %0,%1,%2,%3;" : "=l"(d) : "l"(a), "l"(b), "l"(c)); return d;
}
__device__ __forceinline__ ull fmul2(ull a, ull b) {
    ull d; asm("mul.rn.f32x2 %0,%1,%2;" : "=l"(d) : "l"(a), "l"(b)); return d;
}

// Scratch (static device arrays allowed; cudaMalloc is not)
__device__ float g_Q[Mrows * Dmodel];
__device__ float g_K[Mrows * Dmodel];
__device__ float g_V[Mrows * Dmodel];
__device__ float g_C[Mrows * Dmodel];

// ---------------------------------------------------------------------------
// GEMM: C[M,1024] = X[M,1024] @ W[1024,1024]^T + bias   (row-major, NT)
// Tile 128x128x16, 256 threads, 8x8 per-thread block, f32x2 accumulation.
// ---------------------------------------------------------------------------
#define BM 128
#define BN 128
#define BK 16

__device__ __forceinline__ void gemm_body(const float* __restrict__ X,
                                          const float* __restrict__ W,
                                          const float* __restrict__ bias,
                                          float* __restrict__ C)
{
    __shared__ __align__(16) float As[BK][BM + 4];
    __shared__ __align__(16) float Bs[BK][BN + 4];

    const int tid = threadIdx.x;       // 0..255
    const int tx  = tid & 15;          // n group
    const int ty  = tid >> 4;          // m group
    const int m0  = blockIdx.y * BM;
    const int n0  = blockIdx.x * BN;
    const int lr  = tid >> 2;          // 0..63
    const int lc  = (tid & 3) << 2;    // 0,4,8,12

    ull acc2[8][4];
#pragma unroll
    for (int r = 0; r < 8; r++)
#pragma unroll
        for (int c = 0; c < 4; c++) acc2[r][c] = 0ull;

    for (int k0 = 0; k0 < Dmodel; k0 += BK) {
        float4 a0 = *(const float4*)(X + (size_t)(m0 + lr) * Dmodel + k0 + lc);
        float4 a1 = *(const float4*)(X + (size_t)(m0 + lr + 64) * Dmodel + k0 + lc);
        float4 b0 = *(const float4*)(W + (size_t)(n0 + lr) * Dmodel + k0 + lc);
        float4 b1 = *(const float4*)(W + (size_t)(n0 + lr + 64) * Dmodel + k0 + lc);

        As[lc + 0][lr] = a0.x; As[lc + 1][lr] = a0.y;
        As[lc + 2][lr] = a0.z; As[lc + 3][lr] = a0.w;
        As[lc + 0][lr + 64] = a1.x; As[lc + 1][lr + 64] = a1.y;
        As[lc + 2][lr + 64] = a1.z; As[lc + 3][lr + 64] = a1.w;

        Bs[lc + 0][lr] = b0.x; Bs[lc + 1][lr] = b0.y;
        Bs[lc + 2][lr] = b0.z; Bs[lc + 3][lr] = b0.w;
        Bs[lc + 0][lr + 64] = b1.x; Bs[lc + 1][lr + 64] = b1.y;
        Bs[lc + 2][lr + 64] = b1.z; Bs[lc + 3][lr + 64] = b1.w;

        __syncthreads();

#pragma unroll
        for (int kk = 0; kk < BK; kk++) {
            float a[8];
            *(float4*)&a[0] = *(const float4*)&As[kk][ty * 8];
            *(float4*)&a[4] = *(const float4*)&As[kk][ty * 8 + 4];
            float4 bb0 = *(const float4*)&Bs[kk][tx * 8];
            float4 bb1 = *(const float4*)&Bs[kk][tx * 8 + 4];
            ull b2[4];
            b2[0] = f2pack(bb0.x, bb0.y); b2[1] = f2pack(bb0.z, bb0.w);
            b2[2] = f2pack(bb1.x, bb1.y); b2[3] = f2pack(bb1.z, bb1.w);
#pragma unroll
            for (int r = 0; r < 8; r++) {
                const ull ar = f2pack(a[r], a[r]);
#pragma unroll
                for (int c = 0; c < 4; c++)
                    acc2[r][c] = ffma2(ar, b2[c], acc2[r][c]);
            }
        }
        __syncthreads();
    }

#pragma unroll
    for (int r = 0; r < 8; r++) {
        const int m = m0 + ty * 8 + r;
#pragma unroll
        for (int c = 0; c < 2; c++) {
            const int n = n0 + tx * 8 + c * 4;
            float4 o;
            f2unpack(acc2[r][c * 2 + 0], o.x, o.y);
            f2unpack(acc2[r][c * 2 + 1], o.z, o.w);
            o.x += bias[n + 0]; o.y += bias[n + 1];
            o.z += bias[n + 2]; o.w += bias[n + 3];
            *(float4*)(C + (size_t)m * Dmodel + n) = o;
        }
    }
}

__global__ __launch_bounds__(256) void qkv_gemm(
    const float* __restrict__ q, const float* __restrict__ k, const float* __restrict__ v,
    const float* __restrict__ Wq, const float* __restrict__ bq,
    const float* __restrict__ Wk, const float* __restrict__ bk,
    const float* __restrict__ Wv, const float* __restrict__ bv)
{
    const int which = blockIdx.z;
    const float* X    = (which == 0) ? q  : (which == 1) ? k  : v;
    const float* W    = (which == 0) ? Wq : (which == 1) ? Wk : Wv;
    const float* bias = (which == 0) ? bq : (which == 1) ? bk : bv;
    float* C          = (which == 0) ? g_Q : (which == 1) ? g_K : g_V;
    gemm_body(X, W, bias, C);
}

__global__ __launch_bounds__(256) void out_gemm(const float* __restrict__ Wo,
                                                const float* __restrict__ bo,
                                                float* __restrict__ out)
{
    gemm_body(g_C, Wo, bo, out);
}

// ---------------------------------------------------------------------------
// Flash attention, fp32 with f32x2 math. Tiles: 64 q rows x 64 k rows, DK=64.
// 256 threads (16x16), each thread owns a 4x4 block of S/P and O.
// ---------------------------------------------------------------------------
#define FSTRIDE 68
#define FLASH_SMEM (4 * 64 * FSTRIDE * (int)sizeof(float))   // 69632 B

__global__ __launch_bounds__(256) void flash_attn()
{
    extern __shared__ __align__(16) float sm[];
    float* Qst = sm;                     // [64][68]  (d-major)
    float* Kst = sm + 64 * FSTRIDE;      // [64][68]  (d-major)
    float* Vs  = sm + 2 * 64 * FSTRIDE;  // [64][68]  (j-major)
    float* Pst = sm + 3 * 64 * FSTRIDE;  // [64][68]  (j-major)

    const int tid = threadIdx.x;
    const int tx  = tid & 15;
    const int ty  = tid >> 4;
    const int bh  = blockIdx.y;
    const int b   = bh >> 4;
    const int h   = bh & 15;
    const int q0  = blockIdx.x * 64;

    const float* Qb = g_Q + (size_t)b * Nseq * Dmodel + h * DKh;
    const float* Kb = g_K + (size_t)b * Nseq * Dmodel + h * DKh;
    const float* Vb = g_V + (size_t)b * Nseq * Dmodel + h * DKh;

    const int lr  = tid >> 2;            // 0..63
    const int lc0 = (tid & 3) << 4;      // 0,16,32,48

    // Load Q tile transposed (d-major)
#pragma unroll
    for (int i = 0; i < 4; i++) {
        const int d = lc0 + i * 4;
        float4 qv = *(const float4*)(Qb + (size_t)(q0 + lr) * Dmodel + d);
        Qst[(d + 0) * FSTRIDE + lr] = qv.x;
        Qst[(d + 1) * FSTRIDE + lr] = qv.y;
        Qst[(d + 2) * FSTRIDE + lr] = qv.z;
        Qst[(d + 3) * FSTRIDE + lr] = qv.w;
    }

    ull o2[4][2];
#pragma unroll
    for (int r = 0; r < 4; r++) { o2[r][0] = 0ull; o2[r][1] = 0ull; }
    float mrow[4] = {-1e30f, -1e30f, -1e30f, -1e30f};
    float lrow[4] = {0.0f, 0.0f, 0.0f, 0.0f};

    for (int j0 = 0; j0 < Nseq; j0 += 64) {
        // Load K (transposed) and V (natural)
#pragma unroll
        for (int i = 0; i < 4; i++) {
            const int d = lc0 + i * 4;
            float4 kv = *(const float4*)(Kb + (size_t)(j0 + lr) * Dmodel + d);
            Kst[(d + 0) * FSTRIDE + lr] = kv.x;
            Kst[(d + 1) * FSTRIDE + lr] = kv.y;
            Kst[(d + 2) * FSTRIDE + lr] = kv.z;
            Kst[(d + 3) * FSTRIDE + lr] = kv.w;
            float4 vv = *(const float4*)(Vb + (size_t)(j0 + lr) * Dmodel + d);
            *(float4*)&Vs[lr * FSTRIDE + d] = vv;
        }
        __syncthreads();

        // S = Q @ K^T
        ull s2[4][2];
#pragma unroll
        for (int r = 0; r < 4; r++) { s2[r][0] = 0ull; s2[r][1] = 0ull; }
#pragma unroll 8
        for (int d = 0; d < 64; d++) {
            float4 a  = *(const float4*)&Qst[d * FSTRIDE + ty * 4];
            float4 bb = *(const float4*)&Kst[d * FSTRIDE + tx * 4];
            const ull bp0 = f2pack(bb.x, bb.y);
            const ull bp1 = f2pack(bb.z, bb.w);
            const float av[4] = {a.x, a.y, a.z, a.w};
#pragma unroll
            for (int r = 0; r < 4; r++) {
                const ull ar = f2pack(av[r], av[r]);
                s2[r][0] = ffma2(ar, bp0, s2[r][0]);
                s2[r][1] = ffma2(ar, bp1, s2[r][1]);
            }
        }

        // Online softmax update
#pragma unroll
        for (int r = 0; r < 4; r++) {
            float s0, s1, sv2, s3;
            f2unpack(s2[r][0], s0, s1);
            f2unpack(s2[r][1], sv2, s3);
            s0 *= SCALE; s1 *= SCALE; sv2 *= SCALE; s3 *= SCALE;
            float mx = fmaxf(fmaxf(s0, s1), fmaxf(sv2, s3));
#pragma unroll
            for (int off = 1; off < 16; off <<= 1)
                mx = fmaxf(mx, __shfl_xor_sync(0xffffffffu, mx, off));
            const float mnew = fmaxf(mrow[r], mx);
            const float p0 = __expf(s0 - mnew);
            const float p1 = __expf(s1 - mnew);
            const float p2 = __expf(sv2 - mnew);
            const float p3 = __expf(s3 - mnew);
            float rs = p0 + p1 + p2 + p3;
#pragma unroll
            for (int off = 1; off < 16; off <<= 1)
                rs += __shfl_xor_sync(0xffffffffu, rs, off);
            const float alpha = __expf(mrow[r] - mnew);
            lrow[r] = lrow[r] * alpha + rs;
            mrow[r] = mnew;
            const ull al2 = f2pack(alpha, alpha);
            o2[r][0] = fmul2(o2[r][0], al2);
            o2[r][1] = fmul2(o2[r][1], al2);
            // Store P transposed: Pst[key j][query m]
            Pst[(tx * 4 + 0) * FSTRIDE + ty * 4 + r] = p0;
            Pst[(tx * 4 + 1) * FSTRIDE + ty * 4 + r] = p1;
            Pst[(tx * 4 + 2) * FSTRIDE + ty * 4 + r] = p2;
            Pst[(tx * 4 + 3) * FSTRIDE + ty * 4 + r] = p3;
        }
        __syncthreads();

        // O += P @ V
#pragma unroll 8
        for (int j = 0; j < 64; j++) {
            float4 p  = *(const float4*)&Pst[j * FSTRIDE + ty * 4];
            float4 vv = *(const float4*)&Vs[j * FSTRIDE + tx * 4];
            const ull vp0 = f2pack(vv.x, vv.y);
            const ull vp1 = f2pack(vv.z, vv.w);
            const float pv[4] = {p.x, p.y, p.z, p.w};
#pragma unroll
            for (int r = 0; r < 4; r++) {
                const ull pr = f2pack(pv[r], pv[r]);
                o2[r][0] = ffma2(pr, vp0, o2[r][0]);
                o2[r][1] = ffma2(pr, vp1, o2[r][1]);
            }
        }
        __syncthreads();
    }

    // Epilogue: normalize, write to [b, n, h*64 + d]
    float* Cb = g_C + (size_t)b * Nseq * Dmodel + h * DKh;
#pragma unroll
    for (int r = 0; r < 4; r++) {
        const float inv = 1.0f / lrow[r];
        float4 ov;
        f2unpack(o2[r][0], ov.x, ov.y);
        f2unpack(o2[r][1], ov.z, ov.w);
        ov.x *= inv; ov.y *= inv; ov.z *= inv; ov.w *= inv;
        *(float4*)(Cb + (size_t)(q0 + ty * 4 + r) * Dmodel + tx * 4) = ov;
    }
}

// ---------------------------------------------------------------------------
extern "C" void kernel_launch(void* const* d_in, const int* in_sizes, int n_in,
                              void* d_out, int out_size)
{
    const float* q  = (const float*)d_in[0];
    const float* k  = (const float*)d_in[1];
    const float* v  = (const float*)d_in[2];
    const float* Wq = (const float*)d_in[3];
    const float* bq = (const float*)d_in[4];
    const float* Wk = (const float*)d_in[5];
    const float* bk = (const float*)d_in[6];
    const float* Wv = (const float*)d_in[7];
    const float* bv = (const float*)d_in[8];
    const float* Wo = (const float*)d_in[9];
    const float* bo = (const float*)d_in[10];
    float* out = (float*)d_out;

    cudaFuncSetAttribute(flash_attn, cudaFuncAttributeMaxDynamicSharedMemorySize,
                         FLASH_SMEM);

    dim3 gqkv(Dmodel / BN, Mrows / BM, 3);   // 8 x 32 x 3
    qkv_gemm<<<gqkv, 256>>>(q, k, v, Wq, bq, Wk, bk, Wv, bv);

    dim3 gf(Nseq / 64, Bsz * Hh);            // 32 x 32
    flash_attn<<<gf, 256, FLASH_SMEM>>>();

    dim3 go(Dmodel / BN, Mrows / BM);        // 8 x 32
    out_gemm<<<go, 256>>>(Wo, bo, out);
}

// round 5
// speedup vs baseline: 1.1160x; 1.1117x over previous
#include <cuda_runtime.h>
#include <cuda_bf16.h>

// Problem constants
#define Bsz    2
#define Nseq   2048
#define Dmodel 1024
#define Hh     16
#define DKh    64
#define Mrows  4096
#define SCALE  0.125f

typedef unsigned long long ull;

// ---- packed fp32x2 helpers (flash kernel) ----
__device__ __forceinline__ ull f2pack(float lo, float hi) {
    ull r; asm("mov.b64 %0,{%1,%2};" : "=l"(r) : "f"(lo), "f"(hi)); return r;
}
__device__ __forceinline__ void f2unpack(ull p, float& lo, float& hi) {
    asm("mov.b64 {%0,%1},%2;" : "=f"(lo), "=f"(hi) : "l"(p));
}
__device__ __forceinline__ ull ffma2(ull a, ull b, ull c) {
    ull d; asm("fma.rn.f32x2 %0,%1,%2,%3;" : "=l"(d) : "l"(a), "l"(b), "l"(c)); return d;
}
__device__ __forceinline__ ull fmul2(ull a, ull b) {
    ull d; asm("mul.rn.f32x2 %0,%1,%2;" : "=l"(d) : "l"(a), "l"(b)); return d;
}

// ---- mma.sync / ldmatrix helpers (base sm_80+ ISA; no 'a' feature needed) ----
__device__ __forceinline__ unsigned smem_u32(const void* p) {
    unsigned a;
    asm("{ .reg .u64 t; cvta.to.shared.u64 t, %1; cvt.u32.u64 %0, t; }" : "=r"(a) : "l"(p));
    return a;
}
__device__ __forceinline__ void ldsm_x4(unsigned& r0, unsigned& r1, unsigned& r2, unsigned& r3,
                                        unsigned addr) {
    asm volatile("ldmatrix.sync.aligned.m8n8.x4.shared.b16 {%0,%1,%2,%3}, [%4];"
                 : "=r"(r0), "=r"(r1), "=r"(r2), "=r"(r3) : "r"(addr));
}
__device__ __forceinline__ void mma16816(float* c, const unsigned* a, const unsigned* b) {
    asm volatile("mma.sync.aligned.m16n8k16.row.col.f32.bf16.bf16.f32 "
                 "{%0,%1,%2,%3},{%4,%5,%6,%7},{%8,%9},{%0,%1,%2,%3};"
                 : "+f"(c[0]), "+f"(c[1]), "+f"(c[2]), "+f"(c[3])
                 : "r"(a[0]), "r"(a[1]), "r"(a[2]), "r"(a[3]), "r"(b[0]), "r"(b[1]));
}

// Scratch
__device__ float g_Q[Mrows * Dmodel];
__device__ float g_K[Mrows * Dmodel];
__device__ float g_V[Mrows * Dmodel];
__device__ float g_C[Mrows * Dmodel];

// ---------------------------------------------------------------------------
// HMMA bf16-split GEMM: C[M,1024] = X[M,1024] @ W[1024,1024]^T + bias
// Tile 128x128, 8 warps (2m x 4n), warp tile 64x32, K-chunk 32.
// fp32 = hi_bf16 + lo_bf16; passes: Ahi*Bhi + Ahi*Blo + Alo*Bhi.
// smem stride 40 bf16 (80 B): 16B-aligned rows, LDSM conflict-free.
// ---------------------------------------------------------------------------
#define KC 32
#define SST 40   // smem row stride in bf16 elems

struct GSmem {
    __nv_bfloat16 Ahi[128 * SST];
    __nv_bfloat16 Alo[128 * SST];
    __nv_bfloat16 Bhi[128 * SST];
    __nv_bfloat16 Blo[128 * SST];
};

__device__ __forceinline__ void cvt8_hilo(float4 a, float4 b, uint4& hi, uint4& lo) {
    float f[8] = {a.x, a.y, a.z, a.w, b.x, b.y, b.z, b.w};
    unsigned h[8], l[8];
#pragma unroll
    for (int i = 0; i < 8; i++) {
        __nv_bfloat16 bh = __float2bfloat16_rn(f[i]);
        float r = f[i] - __bfloat162float(bh);
        __nv_bfloat16 bl = __float2bfloat16_rn(r);
        h[i] = (unsigned)__bfloat16_as_ushort(bh);
        l[i] = (unsigned)__bfloat16_as_ushort(bl);
    }
    hi.x = h[0] | (h[1] << 16); hi.y = h[2] | (h[3] << 16);
    hi.z = h[4] | (h[5] << 16); hi.w = h[6] | (h[7] << 16);
    lo.x = l[0] | (l[1] << 16); lo.y = l[2] | (l[3] << 16);
    lo.z = l[4] | (l[5] << 16); lo.w = l[6] | (l[7] << 16);
}

__device__ __forceinline__ void gemm_body(const float* __restrict__ X,
                                          const float* __restrict__ W,
                                          const float* __restrict__ bias,
                                          float* __restrict__ C)
{
    __shared__ __align__(16) GSmem sm;

    const int tid  = threadIdx.x;
    const int wid  = tid >> 5;
    const int lane = tid & 31;
    const int wm   = wid >> 2;          // 0..1  (64-row slab)
    const int wn   = wid & 3;           // 0..3  (32-col slab)
    const int m0   = blockIdx.y * 128;
    const int n0   = blockIdx.x * 128;

    const int row  = tid >> 1;          // 0..127
    const int half = (tid & 1) * 16;    // k offset within chunk
    const float* xrow = X + (size_t)(m0 + row) * Dmodel + half;
    const float* wrow = W + (size_t)(n0 + row) * Dmodel + half;

    float acc[4][4][4];
#pragma unroll
    for (int mt = 0; mt < 4; mt++)
#pragma unroll
        for (int nt = 0; nt < 4; nt++)
#pragma unroll
            for (int i = 0; i < 4; i++) acc[mt][nt][i] = 0.0f;

    // LDSM base addresses for this lane
    const unsigned a_base = smem_u32(sm.Ahi) +
        (unsigned)(((wm * 64 + (lane & 15)) * SST + (lane >> 4) * 8) * 2);
    const unsigned b_base = smem_u32(sm.Bhi) +
        (unsigned)(((wn * 32 + (lane & 15)) * SST + (lane >> 4) * 8) * 2);
    const unsigned lobytes = (unsigned)(128 * SST * 2);   // Ahi->Alo / Bhi->Blo delta

    for (int ch = 0; ch < Dmodel / KC; ch++) {
        const int k0 = ch * KC;
        // Load + split-convert A and B rows into smem
#pragma unroll
        for (int g = 0; g < 2; g++) {
            float4 a0 = *(const float4*)(xrow + k0 + g * 8);
            float4 a1 = *(const float4*)(xrow + k0 + g * 8 + 4);
            uint4 hi, lo;
            cvt8_hilo(a0, a1, hi, lo);
            const int off = row * SST + half + g * 8;
            *(uint4*)&sm.Ahi[off] = hi;
            *(uint4*)&sm.Alo[off] = lo;
        }
#pragma unroll
        for (int g = 0; g < 2; g++) {
            float4 b0 = *(const float4*)(wrow + k0 + g * 8);
            float4 b1 = *(const float4*)(wrow + k0 + g * 8 + 4);
            uint4 hi, lo;
            cvt8_hilo(b0, b1, hi, lo);
            const int off = row * SST + half + g * 8;
            *(uint4*)&sm.Bhi[off] = hi;
            *(uint4*)&sm.Blo[off] = lo;
        }
        __syncthreads();

#pragma unroll
        for (int pass = 0; pass < 3; pass++) {
            const unsigned abase = (pass == 2) ? a_base + lobytes : a_base;
            const unsigned bbase = (pass == 1) ? b_base + lobytes : b_base;
#pragma unroll
            for (int ks = 0; ks < 2; ks++) {
                const unsigned koff = (unsigned)(ks * 16 * 2);
                unsigned af[4][4];
#pragma unroll
                for (int mt = 0; mt < 4; mt++)
                    ldsm_x4(af[mt][0], af[mt][1], af[mt][2], af[mt][3],
                            abase + koff + (unsigned)(mt * 16 * SST * 2));
                unsigned bf[4][2];
#pragma unroll
                for (int np = 0; np < 2; np++) {
                    unsigned r0, r1, r2, r3;
                    ldsm_x4(r0, r1, r2, r3,
                            bbase + koff + (unsigned)(np * 16 * SST * 2));
                    bf[np * 2 + 0][0] = r0; bf[np * 2 + 0][1] = r2;
                    bf[np * 2 + 1][0] = r1; bf[np * 2 + 1][1] = r3;
                }
#pragma unroll
                for (int mt = 0; mt < 4; mt++)
#pragma unroll
                    for (int nt = 0; nt < 4; nt++)
                        mma16816(acc[mt][nt], af[mt], bf[nt]);
            }
        }
        __syncthreads();
    }

    // Epilogue: fragment layout -> gmem, add bias
    const int g   = lane >> 2;
    const int tig = lane & 3;
#pragma unroll
    for (int mt = 0; mt < 4; mt++) {
        const int r0 = m0 + wm * 64 + mt * 16 + g;
#pragma unroll
        for (int nt = 0; nt < 4; nt++) {
            const int cidx = n0 + wn * 32 + nt * 8 + tig * 2;
            const float2 bv = *(const float2*)(bias + cidx);
            float2 o0, o1;
            o0.x = acc[mt][nt][0] + bv.x;
            o0.y = acc[mt][nt][1] + bv.y;
            o1.x = acc[mt][nt][2] + bv.x;
            o1.y = acc[mt][nt][3] + bv.y;
            *(float2*)(C + (size_t)r0 * Dmodel + cidx) = o0;
            *(float2*)(C + (size_t)(r0 + 8) * Dmodel + cidx) = o1;
        }
    }
}

__global__ __launch_bounds__(256) void qkv_gemm(
    const float* __restrict__ q, const float* __restrict__ k, const float* __restrict__ v,
    const float* __restrict__ Wq, const float* __restrict__ bq,
    const float* __restrict__ Wk, const float* __restrict__ bk,
    const float* __restrict__ Wv, const float* __restrict__ bv)
{
    const int which = blockIdx.z;
    const float* X    = (which == 0) ? q  : (which == 1) ? k  : v;
    const float* W    = (which == 0) ? Wq : (which == 1) ? Wk : Wv;
    const float* bias = (which == 0) ? bq : (which == 1) ? bk : bv;
    float* C          = (which == 0) ? g_Q : (which == 1) ? g_K : g_V;
    gemm_body(X, W, bias, C);
}

__global__ __launch_bounds__(256) void out_gemm(const float* __restrict__ Wo,
                                                const float* __restrict__ bo,
                                                float* __restrict__ out)
{
    gemm_body(g_C, Wo, bo, out);
}

// ---------------------------------------------------------------------------
// Flash attention, fp32 with f32x2 math (unchanged; known-good)
// ---------------------------------------------------------------------------
#define FSTRIDE 68
#define FLASH_SMEM (4 * 64 * FSTRIDE * (int)sizeof(float))   // 69632 B

__global__ __launch_bounds__(256) void flash_attn()
{
    extern __shared__ __align__(16) float sm[];
    float* Qst = sm;
    float* Kst = sm + 64 * FSTRIDE;
    float* Vs  = sm + 2 * 64 * FSTRIDE;
    float* Pst = sm + 3 * 64 * FSTRIDE;

    const int tid = threadIdx.x;
    const int tx  = tid & 15;
    const int ty  = tid >> 4;
    const int bh  = blockIdx.y;
    const int b   = bh >> 4;
    const int h   = bh & 15;
    const int q0  = blockIdx.x * 64;

    const float* Qb = g_Q + (size_t)b * Nseq * Dmodel + h * DKh;
    const float* Kb = g_K + (size_t)b * Nseq * Dmodel + h * DKh;
    const float* Vb = g_V + (size_t)b * Nseq * Dmodel + h * DKh;

    const int lr  = tid >> 2;
    const int lc0 = (tid & 3) << 4;

#pragma unroll
    for (int i = 0; i < 4; i++) {
        const int d = lc0 + i * 4;
        float4 qv = *(const float4*)(Qb + (size_t)(q0 + lr) * Dmodel + d);
        Qst[(d + 0) * FSTRIDE + lr] = qv.x;
        Qst[(d + 1) * FSTRIDE + lr] = qv.y;
        Qst[(d + 2) * FSTRIDE + lr] = qv.z;
        Qst[(d + 3) * FSTRIDE + lr] = qv.w;
    }

    ull o2[4][2];
#pragma unroll
    for (int r = 0; r < 4; r++) { o2[r][0] = 0ull; o2[r][1] = 0ull; }
    float mrow[4] = {-1e30f, -1e30f, -1e30f, -1e30f};
    float lrow[4] = {0.0f, 0.0f, 0.0f, 0.0f};

    for (int j0 = 0; j0 < Nseq; j0 += 64) {
#pragma unroll
        for (int i = 0; i < 4; i++) {
            const int d = lc0 + i * 4;
            float4 kv = *(const float4*)(Kb + (size_t)(j0 + lr) * Dmodel + d);
            Kst[(d + 0) * FSTRIDE + lr] = kv.x;
            Kst[(d + 1) * FSTRIDE + lr] = kv.y;
            Kst[(d + 2) * FSTRIDE + lr] = kv.z;
            Kst[(d + 3) * FSTRIDE + lr] = kv.w;
            float4 vv = *(const float4*)(Vb + (size_t)(j0 + lr) * Dmodel + d);
            *(float4*)&Vs[lr * FSTRIDE + d] = vv;
        }
        __syncthreads();

        ull s2[4][2];
#pragma unroll
        for (int r = 0; r < 4; r++) { s2[r][0] = 0ull; s2[r][1] = 0ull; }
#pragma unroll 8
        for (int d = 0; d < 64; d++) {
            float4 a  = *(const float4*)&Qst[d * FSTRIDE + ty * 4];
            float4 bb = *(const float4*)&Kst[d * FSTRIDE + tx * 4];
            const ull bp0 = f2pack(bb.x, bb.y);
            const ull bp1 = f2pack(bb.z, bb.w);
            const float av[4] = {a.x, a.y, a.z, a.w};
#pragma unroll
            for (int r = 0; r < 4; r++) {
                const ull ar = f2pack(av[r], av[r]);
                s2[r][0] = ffma2(ar, bp0, s2[r][0]);
                s2[r][1] = ffma2(ar, bp1, s2[r][1]);
            }
        }

#pragma unroll
        for (int r = 0; r < 4; r++) {
            float s0, s1, sv2, s3;
            f2unpack(s2[r][0], s0, s1);
            f2unpack(s2[r][1], sv2, s3);
            s0 *= SCALE; s1 *= SCALE; sv2 *= SCALE; s3 *= SCALE;
            float mx = fmaxf(fmaxf(s0, s1), fmaxf(sv2, s3));
#pragma unroll
            for (int off = 1; off < 16; off <<= 1)
                mx = fmaxf(mx, __shfl_xor_sync(0xffffffffu, mx, off));
            const float mnew = fmaxf(mrow[r], mx);
            const float p0 = __expf(s0 - mnew);
            const float p1 = __expf(s1 - mnew);
            const float p2 = __expf(sv2 - mnew);
            const float p3 = __expf(s3 - mnew);
            float rs = p0 + p1 + p2 + p3;
#pragma unroll
            for (int off = 1; off < 16; off <<= 1)
                rs += __shfl_xor_sync(0xffffffffu, rs, off);
            const float alpha = __expf(mrow[r] - mnew);
            lrow[r] = lrow[r] * alpha + rs;
            mrow[r] = mnew;
            const ull al2 = f2pack(alpha, alpha);
            o2[r][0] = fmul2(o2[r][0], al2);
            o2[r][1] = fmul2(o2[r][1], al2);
            Pst[(tx * 4 + 0) * FSTRIDE + ty * 4 + r] = p0;
            Pst[(tx * 4 + 1) * FSTRIDE + ty * 4 + r] = p1;
            Pst[(tx * 4 + 2) * FSTRIDE + ty * 4 + r] = p2;
            Pst[(tx * 4 + 3) * FSTRIDE + ty * 4 + r] = p3;
        }
        __syncthreads();

#pragma unroll 8
        for (int j = 0; j < 64; j++) {
            float4 p  = *(const float4*)&Pst[j * FSTRIDE + ty * 4];
            float4 vv = *(const float4*)&Vs[j * FSTRIDE + tx * 4];
            const ull vp0 = f2pack(vv.x, vv.y);
            const ull vp1 = f2pack(vv.z, vv.w);
            const float pv[4] = {p.x, p.y, p.z, p.w};
#pragma unroll
            for (int r = 0; r < 4; r++) {
                const ull pr = f2pack(pv[r], pv[r]);
                o2[r][0] = ffma2(pr, vp0, o2[r][0]);
                o2[r][1] = ffma2(pr, vp1, o2[r][1]);
            }
        }
        __syncthreads();
    }

    float* Cb = g_C + (size_t)b * Nseq * Dmodel + h * DKh;
#pragma unroll
    for (int r = 0; r < 4; r++) {
        const float inv = 1.0f / lrow[r];
        float4 ov;
        f2unpack(o2[r][0], ov.x, ov.y);
        f2unpack(o2[r][1], ov.z, ov.w);
        ov.x *= inv; ov.y *= inv; ov.z *= inv; ov.w *= inv;
        *(float4*)(Cb + (size_t)(q0 + ty * 4 + r) * Dmodel + tx * 4) = ov;
    }
}

// ---------------------------------------------------------------------------
extern "C" void kernel_launch(void* const* d_in, const int* in_sizes, int n_in,
                              void* d_out, int out_size)
{
    const float* q  = (const float*)d_in[0];
    const float* k  = (const float*)d_in[1];
    const float* v  = (const float*)d_in[2];
    const float* Wq = (const float*)d_in[3];
    const float* bq = (const float*)d_in[4];
    const float* Wk = (const float*)d_in[5];
    const float* bk = (const float*)d_in[6];
    const float* Wv = (const float*)d_in[7];
    const float* bv = (const float*)d_in[8];
    const float* Wo = (const float*)d_in[9];
    const float* bo = (const float*)d_in[10];
    float* out = (float*)d_out;

    cudaFuncSetAttribute(flash_attn, cudaFuncAttributeMaxDynamicSharedMemorySize,
                         FLASH_SMEM);

    dim3 gqkv(Dmodel / 128, Mrows / 128, 3);   // 8 x 32 x 3
    qkv_gemm<<<gqkv, 256>>>(q, k, v, Wq, bq, Wk, bk, Wv, bv);

    dim3 gf(Nseq / 64, Bsz * Hh);              // 32 x 32
    flash_attn<<<gf, 256, FLASH_SMEM>>>();

    dim3 go(Dmodel / 128, Mrows / 128);        // 8 x 32
    out_gemm<<<go, 256>>>(Wo, bo, out);
}

// round 6
// speedup vs baseline: 1.7312x; 1.5512x over previous
#include <cuda_runtime.h>
#include <cuda_bf16.h>

// Problem constants
#define Bsz    2
#define Nseq   2048
#define Dmodel 1024
#define Hh     16
#define DKh    64
#define Mrows  4096
#define SCALE  0.125f

typedef unsigned long long ull;

// ---- mma.sync / ldmatrix helpers (base sm_80+ ISA) ----
__device__ __forceinline__ unsigned smem_u32(const void* p) {
    unsigned a;
    asm("{ .reg .u64 t; cvta.to.shared.u64 t, %1; cvt.u32.u64 %0, t; }" : "=r"(a) : "l"(p));
    return a;
}
__device__ __forceinline__ void ldsm_x4(unsigned& r0, unsigned& r1, unsigned& r2, unsigned& r3,
                                        unsigned addr) {
    asm volatile("ldmatrix.sync.aligned.m8n8.x4.shared.b16 {%0,%1,%2,%3}, [%4];"
                 : "=r"(r0), "=r"(r1), "=r"(r2), "=r"(r3) : "r"(addr));
}
__device__ __forceinline__ void ldsm_x4_t(unsigned& r0, unsigned& r1, unsigned& r2, unsigned& r3,
                                          unsigned addr) {
    asm volatile("ldmatrix.sync.aligned.m8n8.x4.trans.shared.b16 {%0,%1,%2,%3}, [%4];"
                 : "=r"(r0), "=r"(r1), "=r"(r2), "=r"(r3) : "r"(addr));
}
__device__ __forceinline__ void mma16816(float* c, const unsigned* a, const unsigned* b) {
    asm volatile("mma.sync.aligned.m16n8k16.row.col.f32.bf16.bf16.f32 "
                 "{%0,%1,%2,%3},{%4,%5,%6,%7},{%8,%9},{%0,%1,%2,%3};"
                 : "+f"(c[0]), "+f"(c[1]), "+f"(c[2]), "+f"(c[3])
                 : "r"(a[0]), "r"(a[1]), "r"(a[2]), "r"(a[3]), "r"(b[0]), "r"(b[1]));
}

// Scratch
__device__ float g_Q[Mrows * Dmodel];
__device__ float g_K[Mrows * Dmodel];
__device__ float g_V[Mrows * Dmodel];
__device__ float g_C[Mrows * Dmodel];

// ---------------------------------------------------------------------------
// split-bf16 conversion helpers
// ---------------------------------------------------------------------------
__device__ __forceinline__ void cvt8_hilo(float4 a, float4 b, uint4& hi, uint4& lo) {
    float f[8] = {a.x, a.y, a.z, a.w, b.x, b.y, b.z, b.w};
    unsigned h[8], l[8];
#pragma unroll
    for (int i = 0; i < 8; i++) {
        __nv_bfloat16 bh = __float2bfloat16_rn(f[i]);
        float r = f[i] - __bfloat162float(bh);
        __nv_bfloat16 bl = __float2bfloat16_rn(r);
        h[i] = (unsigned)__bfloat16_as_ushort(bh);
        l[i] = (unsigned)__bfloat16_as_ushort(bl);
    }
    hi.x = h[0] | (h[1] << 16); hi.y = h[2] | (h[3] << 16);
    hi.z = h[4] | (h[5] << 16); hi.w = h[6] | (h[7] << 16);
    lo.x = l[0] | (l[1] << 16); lo.y = l[2] | (l[3] << 16);
    lo.z = l[4] | (l[5] << 16); lo.w = l[6] | (l[7] << 16);
}

__device__ __forceinline__ void pack_hilo(float x, float y, unsigned& h, unsigned& l) {
    __nv_bfloat16 hx = __float2bfloat16_rn(x);
    __nv_bfloat16 hy = __float2bfloat16_rn(y);
    float rx = x - __bfloat162float(hx);
    float ry = y - __bfloat162float(hy);
    __nv_bfloat16 lx = __float2bfloat16_rn(rx);
    __nv_bfloat16 ly = __float2bfloat16_rn(ry);
    h = (unsigned)__bfloat16_as_ushort(hx) | ((unsigned)__bfloat16_as_ushort(hy) << 16);
    l = (unsigned)__bfloat16_as_ushort(lx) | ((unsigned)__bfloat16_as_ushort(ly) << 16);
}

// ---------------------------------------------------------------------------
// HMMA bf16-split GEMM (unchanged from round 5)
// ---------------------------------------------------------------------------
#define KC 32
#define SST 40

struct GSmem {
    __nv_bfloat16 Ahi[128 * SST];
    __nv_bfloat16 Alo[128 * SST];
    __nv_bfloat16 Bhi[128 * SST];
    __nv_bfloat16 Blo[128 * SST];
};

__device__ __forceinline__ void gemm_body(const float* __restrict__ X,
                                          const float* __restrict__ W,
                                          const float* __restrict__ bias,
                                          float* __restrict__ C)
{
    __shared__ __align__(16) GSmem sm;

    const int tid  = threadIdx.x;
    const int wid  = tid >> 5;
    const int lane = tid & 31;
    const int wm   = wid >> 2;
    const int wn   = wid & 3;
    const int m0   = blockIdx.y * 128;
    const int n0   = blockIdx.x * 128;

    const int row  = tid >> 1;
    const int half = (tid & 1) * 16;
    const float* xrow = X + (size_t)(m0 + row) * Dmodel + half;
    const float* wrow = W + (size_t)(n0 + row) * Dmodel + half;

    float acc[4][4][4];
#pragma unroll
    for (int mt = 0; mt < 4; mt++)
#pragma unroll
        for (int nt = 0; nt < 4; nt++)
#pragma unroll
            for (int i = 0; i < 4; i++) acc[mt][nt][i] = 0.0f;

    const unsigned a_base = smem_u32(sm.Ahi) +
        (unsigned)(((wm * 64 + (lane & 15)) * SST + (lane >> 4) * 8) * 2);
    const unsigned b_base = smem_u32(sm.Bhi) +
        (unsigned)(((wn * 32 + (lane & 15)) * SST + (lane >> 4) * 8) * 2);
    const unsigned lobytes = (unsigned)(128 * SST * 2);

    for (int ch = 0; ch < Dmodel / KC; ch++) {
        const int k0 = ch * KC;
#pragma unroll
        for (int g = 0; g < 2; g++) {
            float4 a0 = *(const float4*)(xrow + k0 + g * 8);
            float4 a1 = *(const float4*)(xrow + k0 + g * 8 + 4);
            uint4 hi, lo;
            cvt8_hilo(a0, a1, hi, lo);
            const int off = row * SST + half + g * 8;
            *(uint4*)&sm.Ahi[off] = hi;
            *(uint4*)&sm.Alo[off] = lo;
        }
#pragma unroll
        for (int g = 0; g < 2; g++) {
            float4 b0 = *(const float4*)(wrow + k0 + g * 8);
            float4 b1 = *(const float4*)(wrow + k0 + g * 8 + 4);
            uint4 hi, lo;
            cvt8_hilo(b0, b1, hi, lo);
            const int off = row * SST + half + g * 8;
            *(uint4*)&sm.Bhi[off] = hi;
            *(uint4*)&sm.Blo[off] = lo;
        }
        __syncthreads();

#pragma unroll
        for (int pass = 0; pass < 3; pass++) {
            const unsigned abase = (pass == 2) ? a_base + lobytes : a_base;
            const unsigned bbase = (pass == 1) ? b_base + lobytes : b_base;
#pragma unroll
            for (int ks = 0; ks < 2; ks++) {
                const unsigned koff = (unsigned)(ks * 16 * 2);
                unsigned af[4][4];
#pragma unroll
                for (int mt = 0; mt < 4; mt++)
                    ldsm_x4(af[mt][0], af[mt][1], af[mt][2], af[mt][3],
                            abase + koff + (unsigned)(mt * 16 * SST * 2));
                unsigned bf[4][2];
#pragma unroll
                for (int np = 0; np < 2; np++) {
                    unsigned r0, r1, r2, r3;
                    ldsm_x4(r0, r1, r2, r3,
                            bbase + koff + (unsigned)(np * 16 * SST * 2));
                    bf[np * 2 + 0][0] = r0; bf[np * 2 + 0][1] = r2;
                    bf[np * 2 + 1][0] = r1; bf[np * 2 + 1][1] = r3;
                }
#pragma unroll
                for (int mt = 0; mt < 4; mt++)
#pragma unroll
                    for (int nt = 0; nt < 4; nt++)
                        mma16816(acc[mt][nt], af[mt], bf[nt]);
            }
        }
        __syncthreads();
    }

    const int g   = lane >> 2;
    const int tig = lane & 3;
#pragma unroll
    for (int mt = 0; mt < 4; mt++) {
        const int r0 = m0 + wm * 64 + mt * 16 + g;
#pragma unroll
        for (int nt = 0; nt < 4; nt++) {
            const int cidx = n0 + wn * 32 + nt * 8 + tig * 2;
            const float2 bv = *(const float2*)(bias + cidx);
            float2 o0, o1;
            o0.x = acc[mt][nt][0] + bv.x;
            o0.y = acc[mt][nt][1] + bv.y;
            o1.x = acc[mt][nt][2] + bv.x;
            o1.y = acc[mt][nt][3] + bv.y;
            *(float2*)(C + (size_t)r0 * Dmodel + cidx) = o0;
            *(float2*)(C + (size_t)(r0 + 8) * Dmodel + cidx) = o1;
        }
    }
}

__global__ __launch_bounds__(256) void qkv_gemm(
    const float* __restrict__ q, const float* __restrict__ k, const float* __restrict__ v,
    const float* __restrict__ Wq, const float* __restrict__ bq,
    const float* __restrict__ Wk, const float* __restrict__ bk,
    const float* __restrict__ Wv, const float* __restrict__ bv)
{
    const int which = blockIdx.z;
    const float* X    = (which == 0) ? q  : (which == 1) ? k  : v;
    const float* W    = (which == 0) ? Wq : (which == 1) ? Wk : Wv;
    const float* bias = (which == 0) ? bq : (which == 1) ? bk : bv;
    float* C          = (which == 0) ? g_Q : (which == 1) ? g_K : g_V;
    gemm_body(X, W, bias, C);
}

__global__ __launch_bounds__(256) void out_gemm(const float* __restrict__ Wo,
                                                const float* __restrict__ bo,
                                                float* __restrict__ out)
{
    gemm_body(g_C, Wo, bo, out);
}

// ---------------------------------------------------------------------------
// Flash attention via HMMA bf16-split.
// CTA: 128 q-rows for one (b,h); 8 warps, 16 rows each; j-tiles of 64.
// S = Q K^T (3-pass split); P kept in registers -> A frags; O += P V (3-pass).
// smem: Qhi/Qlo [128][72], Khi/Klo [64][72], Vhi/Vlo [64][72] bf16.
// ---------------------------------------------------------------------------
#define FST 72
#define FSM_BYTES (2 * (128 + 64 + 64) * FST * 2)   // 73728

__global__ __launch_bounds__(256, 1) void flash_attn()
{
    extern __shared__ __align__(16) __nv_bfloat16 fsm[];
    __nv_bfloat16* Qhi = fsm;
    __nv_bfloat16* Qlo = Qhi + 128 * FST;
    __nv_bfloat16* Khi = Qlo + 128 * FST;
    __nv_bfloat16* Klo = Khi + 64 * FST;
    __nv_bfloat16* Vhi = Klo + 64 * FST;
    __nv_bfloat16* Vlo = Vhi + 64 * FST;

    const int tid  = threadIdx.x;
    const int wid  = tid >> 5;
    const int lane = tid & 31;
    const int tg   = lane & 3;
    const int bh   = blockIdx.y;
    const int b    = bh >> 4;
    const int h    = bh & 15;
    const int q0   = blockIdx.x * 128;

    const float* Qg = g_Q + (size_t)b * Nseq * Dmodel + h * DKh;
    const float* Kg = g_K + (size_t)b * Nseq * Dmodel + h * DKh;
    const float* Vg = g_V + (size_t)b * Nseq * Dmodel + h * DKh;

    // ---- load Q tile (persistent in smem) ----
    {
        const int row  = tid >> 1;
        const int half = (tid & 1) * 32;
        const float* src = Qg + (size_t)(q0 + row) * Dmodel + half;
#pragma unroll
        for (int g2 = 0; g2 < 4; g2++) {
            float4 a0 = *(const float4*)(src + g2 * 8);
            float4 a1 = *(const float4*)(src + g2 * 8 + 4);
            uint4 hi, lo;
            cvt8_hilo(a0, a1, hi, lo);
            const int off = row * FST + half + g2 * 8;
            *(uint4*)&Qhi[off] = hi;
            *(uint4*)&Qlo[off] = lo;
        }
    }
    __syncthreads();

    // ldsm base addresses
    const unsigned qa_hi = smem_u32(Qhi) +
        (unsigned)(((wid * 16 + (lane & 15)) * FST + (lane >> 4) * 8) * 2);
    const unsigned qa_lo = qa_hi + (unsigned)(128 * FST * 2);
    const unsigned kb_hi = smem_u32(Khi) +
        (unsigned)(((lane & 15) * FST + (lane >> 4) * 8) * 2);
    const unsigned kb_lo = kb_hi + (unsigned)(64 * FST * 2);
    const unsigned vb_hi = smem_u32(Vhi) +
        (unsigned)(((lane & 15) * FST + (lane >> 4) * 8) * 2);
    const unsigned vb_lo = vb_hi + (unsigned)(64 * FST * 2);

    // persistent Q fragments (hi and lo) — Q smem never changes
    unsigned aqh[4][4], aql[4][4];
#pragma unroll
    for (int ks = 0; ks < 4; ks++) {
        ldsm_x4(aqh[ks][0], aqh[ks][1], aqh[ks][2], aqh[ks][3], qa_hi + ks * 32);
        ldsm_x4(aql[ks][0], aql[ks][1], aql[ks][2], aql[ks][3], qa_lo + ks * 32);
    }

    float oacc[8][4];
#pragma unroll
    for (int nt = 0; nt < 8; nt++)
#pragma unroll
        for (int i = 0; i < 4; i++) oacc[nt][i] = 0.0f;
    float mr0 = -1e30f, mr1 = -1e30f, lr0 = 0.0f, lr1 = 0.0f;

    const int krow = tid >> 2;
    const int kq   = (tid & 3) * 16;

    for (int jt = 0; jt < Nseq; jt += 64) {
        // K/V gmem loads (issued before barrier, latency hidden behind it)
        const float* ksrc = Kg + (size_t)(jt + krow) * Dmodel + kq;
        const float* vsrc = Vg + (size_t)(jt + krow) * Dmodel + kq;
        float4 kr0 = *(const float4*)(ksrc);
        float4 kr1 = *(const float4*)(ksrc + 4);
        float4 kr2 = *(const float4*)(ksrc + 8);
        float4 kr3 = *(const float4*)(ksrc + 12);
        float4 vr0 = *(const float4*)(vsrc);
        float4 vr1 = *(const float4*)(vsrc + 4);
        float4 vr2 = *(const float4*)(vsrc + 8);
        float4 vr3 = *(const float4*)(vsrc + 12);

        __syncthreads();   // previous tile's MMAs done reading K/V smem
        {
            uint4 hi, lo;
            const int off0 = krow * FST + kq;
            cvt8_hilo(kr0, kr1, hi, lo);
            *(uint4*)&Khi[off0] = hi; *(uint4*)&Klo[off0] = lo;
            cvt8_hilo(kr2, kr3, hi, lo);
            *(uint4*)&Khi[off0 + 8] = hi; *(uint4*)&Klo[off0 + 8] = lo;
            cvt8_hilo(vr0, vr1, hi, lo);
            *(uint4*)&Vhi[off0] = hi; *(uint4*)&Vlo[off0] = lo;
            cvt8_hilo(vr2, vr3, hi, lo);
            *(uint4*)&Vhi[off0 + 8] = hi; *(uint4*)&Vlo[off0 + 8] = lo;
        }
        __syncthreads();   // K/V visible

        // ---- S = Q K^T, 3-pass split ----
        float sacc[8][4];
#pragma unroll
        for (int nt = 0; nt < 8; nt++)
#pragma unroll
            for (int i = 0; i < 4; i++) sacc[nt][i] = 0.0f;

#pragma unroll
        for (int pass = 0; pass < 3; pass++) {
            const unsigned kb = (pass == 1) ? kb_lo : kb_hi;
#pragma unroll
            for (int ks = 0; ks < 4; ks++) {
                const unsigned* aq = (pass == 2) ? aql[ks] : aqh[ks];
#pragma unroll
                for (int jb = 0; jb < 4; jb++) {
                    unsigned r0, r1, r2, r3;
                    ldsm_x4(r0, r1, r2, r3,
                            kb + (unsigned)((jb * 16 * FST + ks * 16) * 2));
                    unsigned bf0[2] = {r0, r2};
                    unsigned bf1[2] = {r1, r3};
                    mma16816(sacc[jb * 2 + 0], aq, bf0);
                    mma16816(sacc[jb * 2 + 1], aq, bf1);
                }
            }
        }

        // ---- online softmax (rows g and g+8 per thread-quad) ----
        float mx0 = -1e30f, mx1 = -1e30f;
#pragma unroll
        for (int nt = 0; nt < 8; nt++) {
            mx0 = fmaxf(mx0, fmaxf(sacc[nt][0], sacc[nt][1]));
            mx1 = fmaxf(mx1, fmaxf(sacc[nt][2], sacc[nt][3]));
        }
        mx0 *= SCALE; mx1 *= SCALE;
        mx0 = fmaxf(mx0, __shfl_xor_sync(0xffffffffu, mx0, 1));
        mx0 = fmaxf(mx0, __shfl_xor_sync(0xffffffffu, mx0, 2));
        mx1 = fmaxf(mx1, __shfl_xor_sync(0xffffffffu, mx1, 1));
        mx1 = fmaxf(mx1, __shfl_xor_sync(0xffffffffu, mx1, 2));
        const float mn0 = fmaxf(mr0, mx0);
        const float mn1 = fmaxf(mr1, mx1);
        const float al0 = __expf(mr0 - mn0);
        const float al1 = __expf(mr1 - mn1);

        unsigned pa_hi[4][4], pa_lo[4][4];
        float rs0 = 0.0f, rs1 = 0.0f;
#pragma unroll
        for (int nt = 0; nt < 8; nt++) {
            const float p0 = __expf(fmaf(sacc[nt][0], SCALE, -mn0));
            const float p1 = __expf(fmaf(sacc[nt][1], SCALE, -mn0));
            const float p2 = __expf(fmaf(sacc[nt][2], SCALE, -mn1));
            const float p3 = __expf(fmaf(sacc[nt][3], SCALE, -mn1));
            rs0 += p0 + p1;
            rs1 += p2 + p3;
            unsigned h01, l01, h23, l23;
            pack_hilo(p0, p1, h01, l01);
            pack_hilo(p2, p3, h23, l23);
            const int t = nt >> 1;
            if ((nt & 1) == 0) {
                pa_hi[t][0] = h01; pa_hi[t][1] = h23;
                pa_lo[t][0] = l01; pa_lo[t][1] = l23;
            } else {
                pa_hi[t][2] = h01; pa_hi[t][3] = h23;
                pa_lo[t][2] = l01; pa_lo[t][3] = l23;
            }
            oacc[nt][0] *= al0; oacc[nt][1] *= al0;
            oacc[nt][2] *= al1; oacc[nt][3] *= al1;
        }
        rs0 += __shfl_xor_sync(0xffffffffu, rs0, 1);
        rs0 += __shfl_xor_sync(0xffffffffu, rs0, 2);
        rs1 += __shfl_xor_sync(0xffffffffu, rs1, 1);
        rs1 += __shfl_xor_sync(0xffffffffu, rs1, 2);
        lr0 = lr0 * al0 + rs0;
        lr1 = lr1 * al1 + rs1;
        mr0 = mn0; mr1 = mn1;

        // ---- O += P V, 3-pass split (V B-frags via trans ldmatrix) ----
#pragma unroll
        for (int pass = 0; pass < 3; pass++) {
            const unsigned vb = (pass == 1) ? vb_lo : vb_hi;
#pragma unroll
            for (int t = 0; t < 4; t++) {
                const unsigned* pa = (pass == 2) ? pa_lo[t] : pa_hi[t];
#pragma unroll
                for (int db = 0; db < 4; db++) {
                    unsigned r0, r1, r2, r3;
                    ldsm_x4_t(r0, r1, r2, r3,
                              vb + (unsigned)((t * 16 * FST + db * 16) * 2));
                    unsigned b0[2] = {r0, r1};
                    unsigned b1[2] = {r2, r3};
                    mma16816(oacc[db * 2 + 0], pa, b0);
                    mma16816(oacc[db * 2 + 1], pa, b1);
                }
            }
        }
    }

    // ---- epilogue ----
    const float inv0 = 1.0f / lr0;
    const float inv1 = 1.0f / lr1;
    float* Cb = g_C + (size_t)b * Nseq * Dmodel + h * DKh;
    const int row0 = q0 + wid * 16 + (lane >> 2);
#pragma unroll
    for (int nt = 0; nt < 8; nt++) {
        const int d = nt * 8 + tg * 2;
        float2 v0, v1;
        v0.x = oacc[nt][0] * inv0; v0.y = oacc[nt][1] * inv0;
        v1.x = oacc[nt][2] * inv1; v1.y = oacc[nt][3] * inv1;
        *(float2*)(Cb + (size_t)row0 * Dmodel + d) = v0;
        *(float2*)(Cb + (size_t)(row0 + 8) * Dmodel + d) = v1;
    }
}

// ---------------------------------------------------------------------------
extern "C" void kernel_launch(void* const* d_in, const int* in_sizes, int n_in,
                              void* d_out, int out_size)
{
    const float* q  = (const float*)d_in[0];
    const float* k  = (const float*)d_in[1];
    const float* v  = (const float*)d_in[2];
    const float* Wq = (const float*)d_in[3];
    const float* bq = (const float*)d_in[4];
    const float* Wk = (const float*)d_in[5];
    const float* bk = (const float*)d_in[6];
    const float* Wv = (const float*)d_in[7];
    const float* bv = (const float*)d_in[8];
    const float* Wo = (const float*)d_in[9];
    const float* bo = (const float*)d_in[10];
    float* out = (float*)d_out;

    cudaFuncSetAttribute(flash_attn, cudaFuncAttributeMaxDynamicSharedMemorySize,
                         FSM_BYTES);

    dim3 gqkv(Dmodel / 128, Mrows / 128, 3);   // 8 x 32 x 3
    qkv_gemm<<<gqkv, 256>>>(q, k, v, Wq, bq, Wk, bk, Wv, bv);

    dim3 gf(Nseq / 128, Bsz * Hh);             // 16 x 32
    flash_attn<<<gf, 256, FSM_BYTES>>>();

    dim3 go(Dmodel / 128, Mrows / 128);        // 8 x 32
    out_gemm<<<go, 256>>>(Wo, bo, out);
}

// round 7
// speedup vs baseline: 2.3725x; 1.3705x over previous
#include <cuda_runtime.h>
#include <cuda_bf16.h>

// Problem constants
#define Bsz    2
#define Nseq   2048
#define Dmodel 1024
#define Hh     16
#define DKh    64
#define Mrows  4096
#define NELEM  (Mrows * Dmodel)     // 4,194,304
#define WELEM  (Dmodel * Dmodel)    // 1,048,576
#define SCALE  0.125f

typedef unsigned long long ull;

// ---- mma.sync / ldmatrix / cp.async helpers (base sm_80+ ISA) ----
__device__ __forceinline__ unsigned smem_u32(const void* p) {
    unsigned a;
    asm("{ .reg .u64 t; cvta.to.shared.u64 t, %1; cvt.u32.u64 %0, t; }" : "=r"(a) : "l"(p));
    return a;
}
__device__ __forceinline__ void ldsm_x4(unsigned& r0, unsigned& r1, unsigned& r2, unsigned& r3,
                                        unsigned addr) {
    asm volatile("ldmatrix.sync.aligned.m8n8.x4.shared.b16 {%0,%1,%2,%3}, [%4];"
                 : "=r"(r0), "=r"(r1), "=r"(r2), "=r"(r3) : "r"(addr));
}
__device__ __forceinline__ void ldsm_x4_t(unsigned& r0, unsigned& r1, unsigned& r2, unsigned& r3,
                                          unsigned addr) {
    asm volatile("ldmatrix.sync.aligned.m8n8.x4.trans.shared.b16 {%0,%1,%2,%3}, [%4];"
                 : "=r"(r0), "=r"(r1), "=r"(r2), "=r"(r3) : "r"(addr));
}
__device__ __forceinline__ void mma16816(float* c, const unsigned* a, const unsigned* b) {
    asm volatile("mma.sync.aligned.m16n8k16.row.col.f32.bf16.bf16.f32 "
                 "{%0,%1,%2,%3},{%4,%5,%6,%7},{%8,%9},{%0,%1,%2,%3};"
                 : "+f"(c[0]), "+f"(c[1]), "+f"(c[2]), "+f"(c[3])
                 : "r"(a[0]), "r"(a[1]), "r"(a[2]), "r"(a[3]), "r"(b[0]), "r"(b[1]));
}
__device__ __forceinline__ void cpa16(unsigned dst, const void* src) {
    asm volatile("cp.async.cg.shared.global [%0], [%1], 16;" :: "r"(dst), "l"(src));
}
__device__ __forceinline__ void cpa_commit() { asm volatile("cp.async.commit_group;"); }
template<int N> __device__ __forceinline__ void cpa_wait() {
    asm volatile("cp.async.wait_group %0;" :: "n"(N));
}

// ---- split helpers ----
__device__ __forceinline__ void pack_hilo(float x, float y, unsigned& h, unsigned& l) {
    __nv_bfloat16 hx = __float2bfloat16_rn(x);
    __nv_bfloat16 hy = __float2bfloat16_rn(y);
    float rx = x - __bfloat162float(hx);
    float ry = y - __bfloat162float(hy);
    __nv_bfloat16 lx = __float2bfloat16_rn(rx);
    __nv_bfloat16 ly = __float2bfloat16_rn(ry);
    h = (unsigned)__bfloat16_as_ushort(hx) | ((unsigned)__bfloat16_as_ushort(hy) << 16);
    l = (unsigned)__bfloat16_as_ushort(lx) | ((unsigned)__bfloat16_as_ushort(ly) << 16);
}

// ---- scratch (bf16 split form) ----
__device__ __nv_bfloat16 g_xh[3 * NELEM];   // split inputs q,k,v
__device__ __nv_bfloat16 g_xl[3 * NELEM];
__device__ __nv_bfloat16 g_wh[4 * WELEM];   // split weights Wq,Wk,Wv,Wo
__device__ __nv_bfloat16 g_wl[4 * WELEM];
__device__ __nv_bfloat16 g_ph[3 * NELEM];   // projected Q,K,V (split)
__device__ __nv_bfloat16 g_pl[3 * NELEM];
__device__ __nv_bfloat16 g_Ch[NELEM];       // attention output (split)
__device__ __nv_bfloat16 g_Cl[NELEM];

// ---------------------------------------------------------------------------
// Convert kernels: fp32 -> (hi, lo) bf16
// ---------------------------------------------------------------------------
__global__ __launch_bounds__(256) void split_inputs(const float* __restrict__ q,
                                                    const float* __restrict__ k,
                                                    const float* __restrict__ v)
{
    const int z = blockIdx.z;
    const float* src = (z == 0) ? q : (z == 1) ? k : v;
    __nv_bfloat16* hi = g_xh + (size_t)z * NELEM;
    __nv_bfloat16* lo = g_xl + (size_t)z * NELEM;
    const size_t i = ((size_t)blockIdx.x * 256 + threadIdx.x) * 4;
    float4 f = *(const float4*)(src + i);
    uint2 h, l;
    pack_hilo(f.x, f.y, h.x, l.x);
    pack_hilo(f.z, f.w, h.y, l.y);
    *(uint2*)(hi + i) = h;
    *(uint2*)(lo + i) = l;
}

__global__ __launch_bounds__(256) void split_weights(const float* __restrict__ wq,
                                                     const float* __restrict__ wk,
                                                     const float* __restrict__ wv,
                                                     const float* __restrict__ wo)
{
    const int z = blockIdx.z;
    const float* src = (z == 0) ? wq : (z == 1) ? wk : (z == 2) ? wv : wo;
    __nv_bfloat16* hi = g_wh + (size_t)z * WELEM;
    __nv_bfloat16* lo = g_wl + (size_t)z * WELEM;
    const size_t i = ((size_t)blockIdx.x * 256 + threadIdx.x) * 4;
    float4 f = *(const float4*)(src + i);
    uint2 h, l;
    pack_hilo(f.x, f.y, h.x, l.x);
    pack_hilo(f.z, f.w, h.y, l.y);
    *(uint2*)(hi + i) = h;
    *(uint2*)(lo + i) = l;
}

// ---------------------------------------------------------------------------
// HMMA split GEMM, cp.async 2-stage: C = X @ W^T + bias
// Tile 128x128, Kc=32, 8 warps (2x4), warp tile 64x32, 3 split passes.
// smem/stage: Ahi|Alo|Bhi|Blo each [128][40] bf16.
// ---------------------------------------------------------------------------
#define KC 32
#define NCH (Dmodel / KC)     // 32
#define SST 40
#define GBUF (128 * SST * 2)  // 10240 B
#define GSTAGE (4 * GBUF)     // 40960 B
#define GSMEM (2 * GSTAGE)    // 81920 B

__device__ __forceinline__ void g_load(unsigned sbase, int stage,
                                       const __nv_bfloat16* Xhi, const __nv_bfloat16* Xlo,
                                       const __nv_bfloat16* Whi, const __nv_bfloat16* Wlo,
                                       int m0, int n0, int k0, int tid)
{
    const int row = tid >> 1;
    const int co  = (tid & 1) * 16;              // element offset within chunk
    const unsigned dst0 = sbase + (unsigned)(stage * GSTAGE + row * 80 + (tid & 1) * 32);
    const size_t asrc = (size_t)(m0 + row) * Dmodel + k0 + co;
    const size_t bsrc = (size_t)(n0 + row) * Dmodel + k0 + co;
    cpa16(dst0,                  Xhi + asrc);
    cpa16(dst0 + 16,             Xhi + asrc + 8);
    cpa16(dst0 + GBUF,           Xlo + asrc);
    cpa16(dst0 + GBUF + 16,      Xlo + asrc + 8);
    cpa16(dst0 + 2 * GBUF,       Whi + bsrc);
    cpa16(dst0 + 2 * GBUF + 16,  Whi + bsrc + 8);
    cpa16(dst0 + 3 * GBUF,       Wlo + bsrc);
    cpa16(dst0 + 3 * GBUF + 16,  Wlo + bsrc + 8);
}

__device__ __forceinline__ void gemm_body(const __nv_bfloat16* __restrict__ Xhi,
                                          const __nv_bfloat16* __restrict__ Xlo,
                                          const __nv_bfloat16* __restrict__ Whi,
                                          const __nv_bfloat16* __restrict__ Wlo,
                                          const float* __restrict__ bias,
                                          __nv_bfloat16* Chi, __nv_bfloat16* Clo,
                                          float* Cf)
{
    extern __shared__ __align__(16) char smg[];
    const unsigned sbase = smem_u32(smg);

    const int tid  = threadIdx.x;
    const int wid  = tid >> 5;
    const int lane = tid & 31;
    const int wm   = wid >> 2;
    const int wn   = wid & 3;
    const int m0   = blockIdx.y * 128;
    const int n0   = blockIdx.x * 128;

    float acc[4][4][4];
#pragma unroll
    for (int mt = 0; mt < 4; mt++)
#pragma unroll
        for (int nt = 0; nt < 4; nt++)
#pragma unroll
            for (int i = 0; i < 4; i++) acc[mt][nt][i] = 0.0f;

    const unsigned a_off = (unsigned)(((wm * 64 + (lane & 15)) * SST + (lane >> 4) * 8) * 2);
    const unsigned b_off = (unsigned)(((wn * 32 + (lane & 15)) * SST + (lane >> 4) * 8) * 2);

    // prologue: stages 0 and 1 in flight
    g_load(sbase, 0, Xhi, Xlo, Whi, Wlo, m0, n0, 0, tid);
    cpa_commit();
    g_load(sbase, 1, Xhi, Xlo, Whi, Wlo, m0, n0, KC, tid);
    cpa_commit();
    cpa_wait<1>();
    __syncthreads();

    for (int ch = 0; ch < NCH; ch++) {
        const unsigned st = sbase + (unsigned)((ch & 1) * GSTAGE);
        const unsigned a_hi = st + a_off;
        const unsigned b_hi = st + 2 * GBUF + b_off;

#pragma unroll
        for (int pass = 0; pass < 3; pass++) {
            const unsigned abase = (pass == 2) ? a_hi + GBUF : a_hi;
            const unsigned bbase = (pass == 1) ? b_hi + GBUF : b_hi;
#pragma unroll
            for (int ks = 0; ks < 2; ks++) {
                const unsigned koff = (unsigned)(ks * 16 * 2);
                unsigned af[4][4];
#pragma unroll
                for (int mt = 0; mt < 4; mt++)
                    ldsm_x4(af[mt][0], af[mt][1], af[mt][2], af[mt][3],
                            abase + koff + (unsigned)(mt * 16 * SST * 2));
                unsigned bf[4][2];
#pragma unroll
                for (int np = 0; np < 2; np++) {
                    unsigned r0, r1, r2, r3;
                    ldsm_x4(r0, r1, r2, r3,
                            bbase + koff + (unsigned)(np * 16 * SST * 2));
                    bf[np * 2 + 0][0] = r0; bf[np * 2 + 0][1] = r2;
                    bf[np * 2 + 1][0] = r1; bf[np * 2 + 1][1] = r3;
                }
#pragma unroll
                for (int mt = 0; mt < 4; mt++)
#pragma unroll
                    for (int nt = 0; nt < 4; nt++)
                        mma16816(acc[mt][nt], af[mt], bf[nt]);
            }
        }
        __syncthreads();   // all warps done with stage ch&1 before overwrite

        if (ch + 1 < NCH) {
            if (ch + 2 < NCH) {
                g_load(sbase, ch & 1, Xhi, Xlo, Whi, Wlo, m0, n0, (ch + 2) * KC, tid);
                cpa_commit();
                cpa_wait<1>();
            } else {
                cpa_wait<0>();
            }
            __syncthreads();
        }
    }

    // epilogue
    const int g   = lane >> 2;
    const int tig = lane & 3;
#pragma unroll
    for (int mt = 0; mt < 4; mt++) {
        const int r0 = m0 + wm * 64 + mt * 16 + g;
#pragma unroll
        for (int nt = 0; nt < 4; nt++) {
            const int cidx = n0 + wn * 32 + nt * 8 + tig * 2;
            const float2 bv = *(const float2*)(bias + cidx);
            const float x0 = acc[mt][nt][0] + bv.x;
            const float x1 = acc[mt][nt][1] + bv.y;
            const float x2 = acc[mt][nt][2] + bv.x;
            const float x3 = acc[mt][nt][3] + bv.y;
            if (Cf) {
                *(float2*)(Cf + (size_t)r0 * Dmodel + cidx) = make_float2(x0, x1);
                *(float2*)(Cf + (size_t)(r0 + 8) * Dmodel + cidx) = make_float2(x2, x3);
            } else {
                unsigned h, l;
                pack_hilo(x0, x1, h, l);
                *(unsigned*)(Chi + (size_t)r0 * Dmodel + cidx) = h;
                *(unsigned*)(Clo + (size_t)r0 * Dmodel + cidx) = l;
                pack_hilo(x2, x3, h, l);
                *(unsigned*)(Chi + (size_t)(r0 + 8) * Dmodel + cidx) = h;
                *(unsigned*)(Clo + (size_t)(r0 + 8) * Dmodel + cidx) = l;
            }
        }
    }
}

__global__ __launch_bounds__(256, 2) void qkv_gemm(const float* __restrict__ bq,
                                                   const float* __restrict__ bk,
                                                   const float* __restrict__ bv)
{
    const int z = blockIdx.z;
    const float* bias = (z == 0) ? bq : (z == 1) ? bk : bv;
    gemm_body(g_xh + (size_t)z * NELEM, g_xl + (size_t)z * NELEM,
              g_wh + (size_t)z * WELEM, g_wl + (size_t)z * WELEM,
              bias,
              g_ph + (size_t)z * NELEM, g_pl + (size_t)z * NELEM, nullptr);
}

__global__ __launch_bounds__(256, 2) void out_gemm(const float* __restrict__ bo,
                                                   float* __restrict__ out)
{
    gemm_body(g_Ch, g_Cl,
              g_wh + (size_t)3 * WELEM, g_wl + (size_t)3 * WELEM,
              bo, nullptr, nullptr, out);
}

// ---------------------------------------------------------------------------
// Flash attention, HMMA split, cp.async 2-stage K/V pipeline.
// CTA: 128 q-rows x (b,h); 8 warps x 16 rows; j-tiles of 64.
// smem: Qhi|Qlo [128][72] + 2 stages of (Khi|Klo|Vhi|Vlo [64][72]).
// ---------------------------------------------------------------------------
#define FST 72
#define QBUF (128 * FST * 2)      // 18432 B
#define KVBUF (64 * FST * 2)      // 9216 B
#define KVSTAGE (4 * KVBUF)       // 36864 B
#define FSMEM (2 * QBUF + 2 * KVSTAGE)   // 110592 B

__device__ __forceinline__ void f_loadKV(unsigned kvbase, int stage, int jt,
                                         const __nv_bfloat16* Kh, const __nv_bfloat16* Kl,
                                         const __nv_bfloat16* Vh, const __nv_bfloat16* Vl,
                                         int tid)
{
    const int row = tid >> 2;
    const int c2  = tid & 3;
    const unsigned dst0 = kvbase + (unsigned)(stage * KVSTAGE + row * 144 + c2 * 32);
    const size_t src = (size_t)(jt + row) * Dmodel + c2 * 16;
    cpa16(dst0,                  Kh + src);
    cpa16(dst0 + 16,             Kh + src + 8);
    cpa16(dst0 + KVBUF,          Kl + src);
    cpa16(dst0 + KVBUF + 16,     Kl + src + 8);
    cpa16(dst0 + 2 * KVBUF,      Vh + src);
    cpa16(dst0 + 2 * KVBUF + 16, Vh + src + 8);
    cpa16(dst0 + 3 * KVBUF,      Vl + src);
    cpa16(dst0 + 3 * KVBUF + 16, Vl + src + 8);
}

__global__ __launch_bounds__(256, 1) void flash_attn()
{
    extern __shared__ __align__(16) char smf[];
    const unsigned sbase  = smem_u32(smf);
    const unsigned kvbase = sbase + 2 * QBUF;

    const int tid  = threadIdx.x;
    const int wid  = tid >> 5;
    const int lane = tid & 31;
    const int tg   = lane & 3;
    const int bh   = blockIdx.y;
    const int b    = bh >> 4;
    const int h    = bh & 15;
    const int q0   = blockIdx.x * 128;

    const size_t hoff = (size_t)b * Nseq * Dmodel + h * DKh;
    const __nv_bfloat16* Qh = g_ph + hoff;
    const __nv_bfloat16* Ql = g_pl + hoff;
    const __nv_bfloat16* Kh = g_ph + NELEM + hoff;
    const __nv_bfloat16* Kl = g_pl + NELEM + hoff;
    const __nv_bfloat16* Vh = g_ph + 2 * NELEM + hoff;
    const __nv_bfloat16* Vl = g_pl + 2 * NELEM + hoff;

    // prologue: Q + KV tile0 (group 0), KV tile1 (group 1)
    {
        const int row = tid >> 1;
        const int c4  = tid & 1;
        const unsigned dq = sbase + (unsigned)(row * 144 + c4 * 64);
        const size_t src = (size_t)(q0 + row) * Dmodel + c4 * 32;
#pragma unroll
        for (int j = 0; j < 4; j++) {
            cpa16(dq + j * 16,        Qh + src + j * 8);
            cpa16(dq + QBUF + j * 16, Ql + src + j * 8);
        }
    }
    f_loadKV(kvbase, 0, 0, Kh, Kl, Vh, Vl, tid);
    cpa_commit();
    f_loadKV(kvbase, 1, 64, Kh, Kl, Vh, Vl, tid);
    cpa_commit();
    cpa_wait<1>();
    __syncthreads();

    // persistent Q fragments
    const unsigned qa_hi = sbase +
        (unsigned)(((wid * 16 + (lane & 15)) * FST + (lane >> 4) * 8) * 2);
    const unsigned qa_lo = qa_hi + QBUF;
    unsigned aqh[4][4], aql[4][4];
#pragma unroll
    for (int ks = 0; ks < 4; ks++) {
        ldsm_x4(aqh[ks][0], aqh[ks][1], aqh[ks][2], aqh[ks][3], qa_hi + ks * 32);
        ldsm_x4(aql[ks][0], aql[ks][1], aql[ks][2], aql[ks][3], qa_lo + ks * 32);
    }

    const unsigned kb_off = (unsigned)(((lane & 15) * FST + (lane >> 4) * 8) * 2);

    float oacc[8][4];
#pragma unroll
    for (int nt = 0; nt < 8; nt++)
#pragma unroll
        for (int i = 0; i < 4; i++) oacc[nt][i] = 0.0f;
    float mr0 = -1e30f, mr1 = -1e30f, lr0 = 0.0f, lr1 = 0.0f;

    const int NT = Nseq / 64;   // 32
    for (int jt = 0; jt < NT; jt++) {
        const unsigned st = kvbase + (unsigned)((jt & 1) * KVSTAGE);
        const unsigned kb_hi = st + kb_off;
        const unsigned kb_lo = kb_hi + KVBUF;
        const unsigned vb_hi = st + 2 * KVBUF + kb_off;
        const unsigned vb_lo = vb_hi + KVBUF;

        // ---- S = Q K^T, 3-pass split ----
        float sacc[8][4];
#pragma unroll
        for (int nt = 0; nt < 8; nt++)
#pragma unroll
            for (int i = 0; i < 4; i++) sacc[nt][i] = 0.0f;

#pragma unroll
        for (int pass = 0; pass < 3; pass++) {
            const unsigned kb = (pass == 1) ? kb_lo : kb_hi;
#pragma unroll
            for (int ks = 0; ks < 4; ks++) {
                const unsigned* aq = (pass == 2) ? aql[ks] : aqh[ks];
#pragma unroll
                for (int jb = 0; jb < 4; jb++) {
                    unsigned r0, r1, r2, r3;
                    ldsm_x4(r0, r1, r2, r3,
                            kb + (unsigned)((jb * 16 * FST + ks * 16) * 2));
                    unsigned bf0[2] = {r0, r2};
                    unsigned bf1[2] = {r1, r3};
                    mma16816(sacc[jb * 2 + 0], aq, bf0);
                    mma16816(sacc[jb * 2 + 1], aq, bf1);
                }
            }
        }

        // ---- online softmax ----
        float mx0 = -1e30f, mx1 = -1e30f;
#pragma unroll
        for (int nt = 0; nt < 8; nt++) {
            mx0 = fmaxf(mx0, fmaxf(sacc[nt][0], sacc[nt][1]));
            mx1 = fmaxf(mx1, fmaxf(sacc[nt][2], sacc[nt][3]));
        }
        mx0 *= SCALE; mx1 *= SCALE;
        mx0 = fmaxf(mx0, __shfl_xor_sync(0xffffffffu, mx0, 1));
        mx0 = fmaxf(mx0, __shfl_xor_sync(0xffffffffu, mx0, 2));
        mx1 = fmaxf(mx1, __shfl_xor_sync(0xffffffffu, mx1, 1));
        mx1 = fmaxf(mx1, __shfl_xor_sync(0xffffffffu, mx1, 2));
        const float mn0 = fmaxf(mr0, mx0);
        const float mn1 = fmaxf(mr1, mx1);
        const float al0 = __expf(mr0 - mn0);
        const float al1 = __expf(mr1 - mn1);

        unsigned pa_hi[4][4], pa_lo[4][4];
        float rs0 = 0.0f, rs1 = 0.0f;
#pragma unroll
        for (int nt = 0; nt < 8; nt++) {
            const float p0 = __expf(fmaf(sacc[nt][0], SCALE, -mn0));
            const float p1 = __expf(fmaf(sacc[nt][1], SCALE, -mn0));
            const float p2 = __expf(fmaf(sacc[nt][2], SCALE, -mn1));
            const float p3 = __expf(fmaf(sacc[nt][3], SCALE, -mn1));
            rs0 += p0 + p1;
            rs1 += p2 + p3;
            unsigned h01, l01, h23, l23;
            pack_hilo(p0, p1, h01, l01);
            pack_hilo(p2, p3, h23, l23);
            const int t = nt >> 1;
            if ((nt & 1) == 0) {
                pa_hi[t][0] = h01; pa_hi[t][1] = h23;
                pa_lo[t][0] = l01; pa_lo[t][1] = l23;
            } else {
                pa_hi[t][2] = h01; pa_hi[t][3] = h23;
                pa_lo[t][2] = l01; pa_lo[t][3] = l23;
            }
            oacc[nt][0] *= al0; oacc[nt][1] *= al0;
            oacc[nt][2] *= al1; oacc[nt][3] *= al1;
        }
        rs0 += __shfl_xor_sync(0xffffffffu, rs0, 1);
        rs0 += __shfl_xor_sync(0xffffffffu, rs0, 2);
        rs1 += __shfl_xor_sync(0xffffffffu, rs1, 1);
        rs1 += __shfl_xor_sync(0xffffffffu, rs1, 2);
        lr0 = lr0 * al0 + rs0;
        lr1 = lr1 * al1 + rs1;
        mr0 = mn0; mr1 = mn1;

        // ---- O += P V, 3-pass split ----
#pragma unroll
        for (int pass = 0; pass < 3; pass++) {
            const unsigned vb = (pass == 1) ? vb_lo : vb_hi;
#pragma unroll
            for (int t = 0; t < 4; t++) {
                const unsigned* pa = (pass == 2) ? pa_lo[t] : pa_hi[t];
#pragma unroll
                for (int db = 0; db < 4; db++) {
                    unsigned r0, r1, r2, r3;
                    ldsm_x4_t(r0, r1, r2, r3,
                              vb + (unsigned)((t * 16 * FST + db * 16) * 2));
                    unsigned b0[2] = {r0, r1};
                    unsigned b1[2] = {r2, r3};
                    mma16816(oacc[db * 2 + 0], pa, b0);
                    mma16816(oacc[db * 2 + 1], pa, b1);
                }
            }
        }

        __syncthreads();   // stage jt&1 consumed by all warps
        if (jt + 1 < NT) {
            if (jt + 2 < NT) {
                f_loadKV(kvbase, jt & 1, (jt + 2) * 64, Kh, Kl, Vh, Vl, tid);
                cpa_commit();
                cpa_wait<1>();
            } else {
                cpa_wait<0>();
            }
            __syncthreads();
        }
    }

    // ---- epilogue: write attention out in split form ----
    const float inv0 = 1.0f / lr0;
    const float inv1 = 1.0f / lr1;
    __nv_bfloat16* Ch = g_Ch + hoff;
    __nv_bfloat16* Cl = g_Cl + hoff;
    const int row0 = q0 + wid * 16 + (lane >> 2);
#pragma unroll
    for (int nt = 0; nt < 8; nt++) {
        const int d = nt * 8 + tg * 2;
        unsigned h2, l2;
        pack_hilo(oacc[nt][0] * inv0, oacc[nt][1] * inv0, h2, l2);
        *(unsigned*)(Ch + (size_t)row0 * Dmodel + d) = h2;
        *(unsigned*)(Cl + (size_t)row0 * Dmodel + d) = l2;
        pack_hilo(oacc[nt][2] * inv1, oacc[nt][3] * inv1, h2, l2);
        *(unsigned*)(Ch + (size_t)(row0 + 8) * Dmodel + d) = h2;
        *(unsigned*)(Cl + (size_t)(row0 + 8) * Dmodel + d) = l2;
    }
}

// ---------------------------------------------------------------------------
extern "C" void kernel_launch(void* const* d_in, const int* in_sizes, int n_in,
                              void* d_out, int out_size)
{
    const float* q  = (const float*)d_in[0];
    const float* k  = (const float*)d_in[1];
    const float* v  = (const float*)d_in[2];
    const float* Wq = (const float*)d_in[3];
    const float* bq = (const float*)d_in[4];
    const float* Wk = (const float*)d_in[5];
    const float* bk = (const float*)d_in[6];
    const float* Wv = (const float*)d_in[7];
    const float* bv = (const float*)d_in[8];
    const float* Wo = (const float*)d_in[9];
    const float* bo = (const float*)d_in[10];
    float* out = (float*)d_out;

    cudaFuncSetAttribute(flash_attn, cudaFuncAttributeMaxDynamicSharedMemorySize, FSMEM);
    cudaFuncSetAttribute(qkv_gemm, cudaFuncAttributeMaxDynamicSharedMemorySize, GSMEM);
    cudaFuncSetAttribute(out_gemm, cudaFuncAttributeMaxDynamicSharedMemorySize, GSMEM);

    split_inputs<<<dim3(NELEM / 1024, 1, 3), 256>>>(q, k, v);
    split_weights<<<dim3(WELEM / 1024, 1, 4), 256>>>(Wq, Wk, Wv, Wo);

    dim3 gqkv(Dmodel / 128, Mrows / 128, 3);   // 8 x 32 x 3
    qkv_gemm<<<gqkv, 256, GSMEM>>>(bq, bk, bv);

    dim3 gf(Nseq / 128, Bsz * Hh);             // 16 x 32
    flash_attn<<<gf, 256, FSMEM>>>();

    dim3 go(Dmodel / 128, Mrows / 128);        // 8 x 32
    out_gemm<<<go, 256, GSMEM>>>(bo, out);
}

// round 8
// speedup vs baseline: 3.3440x; 1.4095x over previous
#include <cuda_runtime.h>
#include <cuda_bf16.h>
#include <cuda_fp16.h>

// Problem constants
#define Bsz    2
#define Nseq   2048
#define Dmodel 1024
#define Hh     16
#define DKh    64
#define Mrows  4096
#define NELEM  (Mrows * Dmodel)     // 4,194,304
#define WELEM  (Dmodel * Dmodel)    // 1,048,576
#define SCALE  0.125f

typedef unsigned long long ull;

// ---- mma.sync / ldmatrix / cp.async helpers (base sm_80+ ISA) ----
__device__ __forceinline__ unsigned smem_u32(const void* p) {
    unsigned a;
    asm("{ .reg .u64 t; cvta.to.shared.u64 t, %1; cvt.u32.u64 %0, t; }" : "=r"(a) : "l"(p));
    return a;
}
__device__ __forceinline__ void ldsm_x4(unsigned& r0, unsigned& r1, unsigned& r2, unsigned& r3,
                                        unsigned addr) {
    asm volatile("ldmatrix.sync.aligned.m8n8.x4.shared.b16 {%0,%1,%2,%3}, [%4];"
                 : "=r"(r0), "=r"(r1), "=r"(r2), "=r"(r3) : "r"(addr));
}
__device__ __forceinline__ void ldsm_x4_t(unsigned& r0, unsigned& r1, unsigned& r2, unsigned& r3,
                                          unsigned addr) {
    asm volatile("ldmatrix.sync.aligned.m8n8.x4.trans.shared.b16 {%0,%1,%2,%3}, [%4];"
                 : "=r"(r0), "=r"(r1), "=r"(r2), "=r"(r3) : "r"(addr));
}
__device__ __forceinline__ void mma16816(float* c, const unsigned* a, const unsigned* b) {
    asm volatile("mma.sync.aligned.m16n8k16.row.col.f32.bf16.bf16.f32 "
                 "{%0,%1,%2,%3},{%4,%5,%6,%7},{%8,%9},{%0,%1,%2,%3};"
                 : "+f"(c[0]), "+f"(c[1]), "+f"(c[2]), "+f"(c[3])
                 : "r"(a[0]), "r"(a[1]), "r"(a[2]), "r"(a[3]), "r"(b[0]), "r"(b[1]));
}
__device__ __forceinline__ void mma16816h(float* c, const unsigned* a, const unsigned* b) {
    asm volatile("mma.sync.aligned.m16n8k16.row.col.f32.f16.f16.f32 "
                 "{%0,%1,%2,%3},{%4,%5,%6,%7},{%8,%9},{%0,%1,%2,%3};"
                 : "+f"(c[0]), "+f"(c[1]), "+f"(c[2]), "+f"(c[3])
                 : "r"(a[0]), "r"(a[1]), "r"(a[2]), "r"(a[3]), "r"(b[0]), "r"(b[1]));
}
__device__ __forceinline__ void cpa16(unsigned dst, const void* src) {
    asm volatile("cp.async.cg.shared.global [%0], [%1], 16;" :: "r"(dst), "l"(src));
}
__device__ __forceinline__ void cpa_commit() { asm volatile("cp.async.commit_group;"); }
template<int N> __device__ __forceinline__ void cpa_wait() {
    asm volatile("cp.async.wait_group %0;" :: "n"(N));
}

// ---- split / pack helpers ----
__device__ __forceinline__ void pack_hilo(float x, float y, unsigned& h, unsigned& l) {
    __nv_bfloat16 hx = __float2bfloat16_rn(x);
    __nv_bfloat16 hy = __float2bfloat16_rn(y);
    float rx = x - __bfloat162float(hx);
    float ry = y - __bfloat162float(hy);
    __nv_bfloat16 lx = __float2bfloat16_rn(rx);
    __nv_bfloat16 ly = __float2bfloat16_rn(ry);
    h = (unsigned)__bfloat16_as_ushort(hx) | ((unsigned)__bfloat16_as_ushort(hy) << 16);
    l = (unsigned)__bfloat16_as_ushort(lx) | ((unsigned)__bfloat16_as_ushort(ly) << 16);
}
__device__ __forceinline__ unsigned packf16(float x, float y) {
    __half2 t = __floats2half2_rn(x, y);
    return *reinterpret_cast<unsigned*>(&t);
}

// ---- scratch ----
__device__ __nv_bfloat16 g_xh[3 * NELEM];   // split inputs q,k,v
__device__ __nv_bfloat16 g_xl[3 * NELEM];
__device__ __nv_bfloat16 g_wh[4 * WELEM];   // split weights
__device__ __nv_bfloat16 g_wl[4 * WELEM];
__device__ __half        g_pf[3 * NELEM];   // projected Q(scaled),K,V in fp16
__device__ __nv_bfloat16 g_Ch[NELEM];       // attention output (split bf16)
__device__ __nv_bfloat16 g_Cl[NELEM];

// ---------------------------------------------------------------------------
// Convert kernels
// ---------------------------------------------------------------------------
__global__ __launch_bounds__(256) void split_inputs(const float* __restrict__ q,
                                                    const float* __restrict__ k,
                                                    const float* __restrict__ v)
{
    const int z = blockIdx.z;
    const float* src = (z == 0) ? q : (z == 1) ? k : v;
    __nv_bfloat16* hi = g_xh + (size_t)z * NELEM;
    __nv_bfloat16* lo = g_xl + (size_t)z * NELEM;
    const size_t i = ((size_t)blockIdx.x * 256 + threadIdx.x) * 4;
    float4 f = *(const float4*)(src + i);
    uint2 h, l;
    pack_hilo(f.x, f.y, h.x, l.x);
    pack_hilo(f.z, f.w, h.y, l.y);
    *(uint2*)(hi + i) = h;
    *(uint2*)(lo + i) = l;
}

__global__ __launch_bounds__(256) void split_weights(const float* __restrict__ wq,
                                                     const float* __restrict__ wk,
                                                     const float* __restrict__ wv,
                                                     const float* __restrict__ wo)
{
    const int z = blockIdx.z;
    const float* src = (z == 0) ? wq : (z == 1) ? wk : (z == 2) ? wv : wo;
    __nv_bfloat16* hi = g_wh + (size_t)z * WELEM;
    __nv_bfloat16* lo = g_wl + (size_t)z * WELEM;
    const size_t i = ((size_t)blockIdx.x * 256 + threadIdx.x) * 4;
    float4 f = *(const float4*)(src + i);
    uint2 h, l;
    pack_hilo(f.x, f.y, h.x, l.x);
    pack_hilo(f.z, f.w, h.y, l.y);
    *(uint2*)(hi + i) = h;
    *(uint2*)(lo + i) = l;
}

// ---------------------------------------------------------------------------
// HMMA split GEMM, cp.async 2-stage (bf16 3-pass, unchanged math)
// Epilogue: either fp16 (scaled) or fp32 output.
// ---------------------------------------------------------------------------
#define KC 32
#define NCH (Dmodel / KC)
#define SST 40
#define GBUF (128 * SST * 2)
#define GSTAGE (4 * GBUF)
#define GSMEM (2 * GSTAGE)    // 81920

__device__ __forceinline__ void g_load(unsigned sbase, int stage,
                                       const __nv_bfloat16* Xhi, const __nv_bfloat16* Xlo,
                                       const __nv_bfloat16* Whi, const __nv_bfloat16* Wlo,
                                       int m0, int n0, int k0, int tid)
{
    const int row = tid >> 1;
    const int co  = (tid & 1) * 16;
    const unsigned dst0 = sbase + (unsigned)(stage * GSTAGE + row * 80 + (tid & 1) * 32);
    const size_t asrc = (size_t)(m0 + row) * Dmodel + k0 + co;
    const size_t bsrc = (size_t)(n0 + row) * Dmodel + k0 + co;
    cpa16(dst0,                  Xhi + asrc);
    cpa16(dst0 + 16,             Xhi + asrc + 8);
    cpa16(dst0 + GBUF,           Xlo + asrc);
    cpa16(dst0 + GBUF + 16,      Xlo + asrc + 8);
    cpa16(dst0 + 2 * GBUF,       Whi + bsrc);
    cpa16(dst0 + 2 * GBUF + 16,  Whi + bsrc + 8);
    cpa16(dst0 + 3 * GBUF,       Wlo + bsrc);
    cpa16(dst0 + 3 * GBUF + 16,  Wlo + bsrc + 8);
}

__device__ __forceinline__ void gemm_body(const __nv_bfloat16* __restrict__ Xhi,
                                          const __nv_bfloat16* __restrict__ Xlo,
                                          const __nv_bfloat16* __restrict__ Whi,
                                          const __nv_bfloat16* __restrict__ Wlo,
                                          const float* __restrict__ bias,
                                          __half* C16, float* Cf, float cscale)
{
    extern __shared__ __align__(16) char smg[];
    const unsigned sbase = smem_u32(smg);

    const int tid  = threadIdx.x;
    const int wid  = tid >> 5;
    const int lane = tid & 31;
    const int wm   = wid >> 2;
    const int wn   = wid & 3;
    const int m0   = blockIdx.y * 128;
    const int n0   = blockIdx.x * 128;

    float acc[4][4][4];
#pragma unroll
    for (int mt = 0; mt < 4; mt++)
#pragma unroll
        for (int nt = 0; nt < 4; nt++)
#pragma unroll
            for (int i = 0; i < 4; i++) acc[mt][nt][i] = 0.0f;

    const unsigned a_off = (unsigned)(((wm * 64 + (lane & 15)) * SST + (lane >> 4) * 8) * 2);
    const unsigned b_off = (unsigned)(((wn * 32 + (lane & 15)) * SST + (lane >> 4) * 8) * 2);

    g_load(sbase, 0, Xhi, Xlo, Whi, Wlo, m0, n0, 0, tid);
    cpa_commit();
    g_load(sbase, 1, Xhi, Xlo, Whi, Wlo, m0, n0, KC, tid);
    cpa_commit();
    cpa_wait<1>();
    __syncthreads();

    for (int ch = 0; ch < NCH; ch++) {
        const unsigned st = sbase + (unsigned)((ch & 1) * GSTAGE);
        const unsigned a_hi = st + a_off;
        const unsigned b_hi = st + 2 * GBUF + b_off;

#pragma unroll
        for (int pass = 0; pass < 3; pass++) {
            const unsigned abase = (pass == 2) ? a_hi + GBUF : a_hi;
            const unsigned bbase = (pass == 1) ? b_hi + GBUF : b_hi;
#pragma unroll
            for (int ks = 0; ks < 2; ks++) {
                const unsigned koff = (unsigned)(ks * 16 * 2);
                unsigned af[4][4];
#pragma unroll
                for (int mt = 0; mt < 4; mt++)
                    ldsm_x4(af[mt][0], af[mt][1], af[mt][2], af[mt][3],
                            abase + koff + (unsigned)(mt * 16 * SST * 2));
                unsigned bf[4][2];
#pragma unroll
                for (int np = 0; np < 2; np++) {
                    unsigned r0, r1, r2, r3;
                    ldsm_x4(r0, r1, r2, r3,
                            bbase + koff + (unsigned)(np * 16 * SST * 2));
                    bf[np * 2 + 0][0] = r0; bf[np * 2 + 0][1] = r2;
                    bf[np * 2 + 1][0] = r1; bf[np * 2 + 1][1] = r3;
                }
#pragma unroll
                for (int mt = 0; mt < 4; mt++)
#pragma unroll
                    for (int nt = 0; nt < 4; nt++)
                        mma16816(acc[mt][nt], af[mt], bf[nt]);
            }
        }
        __syncthreads();

        if (ch + 1 < NCH) {
            if (ch + 2 < NCH) {
                g_load(sbase, ch & 1, Xhi, Xlo, Whi, Wlo, m0, n0, (ch + 2) * KC, tid);
                cpa_commit();
                cpa_wait<1>();
            } else {
                cpa_wait<0>();
            }
            __syncthreads();
        }
    }

    const int g   = lane >> 2;
    const int tig = lane & 3;
#pragma unroll
    for (int mt = 0; mt < 4; mt++) {
        const int r0 = m0 + wm * 64 + mt * 16 + g;
#pragma unroll
        for (int nt = 0; nt < 4; nt++) {
            const int cidx = n0 + wn * 32 + nt * 8 + tig * 2;
            const float2 bv = *(const float2*)(bias + cidx);
            const float x0 = acc[mt][nt][0] + bv.x;
            const float x1 = acc[mt][nt][1] + bv.y;
            const float x2 = acc[mt][nt][2] + bv.x;
            const float x3 = acc[mt][nt][3] + bv.y;
            if (Cf) {
                *(float2*)(Cf + (size_t)r0 * Dmodel + cidx) = make_float2(x0, x1);
                *(float2*)(Cf + (size_t)(r0 + 8) * Dmodel + cidx) = make_float2(x2, x3);
            } else {
                *(unsigned*)(C16 + (size_t)r0 * Dmodel + cidx) =
                    packf16(x0 * cscale, x1 * cscale);
                *(unsigned*)(C16 + (size_t)(r0 + 8) * Dmodel + cidx) =
                    packf16(x2 * cscale, x3 * cscale);
            }
        }
    }
}

__global__ __launch_bounds__(256, 2) void qkv_gemm(const float* __restrict__ bq,
                                                   const float* __restrict__ bk,
                                                   const float* __restrict__ bv)
{
    const int z = blockIdx.z;
    const float* bias = (z == 0) ? bq : (z == 1) ? bk : bv;
    const float cs = (z == 0) ? SCALE : 1.0f;   // fold softmax scale into Q
    gemm_body(g_xh + (size_t)z * NELEM, g_xl + (size_t)z * NELEM,
              g_wh + (size_t)z * WELEM, g_wl + (size_t)z * WELEM,
              bias, g_pf + (size_t)z * NELEM, nullptr, cs);
}

__global__ __launch_bounds__(256, 2) void out_gemm(const float* __restrict__ bo,
                                                   float* __restrict__ out)
{
    gemm_body(g_Ch, g_Cl,
              g_wh + (size_t)3 * WELEM, g_wl + (size_t)3 * WELEM,
              bo, nullptr, out, 1.0f);
}

// ---------------------------------------------------------------------------
// Flash attention, fp16 single-pass HMMA, cp.async 2-stage K/V pipeline.
// CTA: 128 q-rows x (b,h); 8 warps x 16 rows; j-tiles of 64.
// smem: Qf [128][72] + 2 stages of (Kf|Vf [64][72]) fp16.
// ---------------------------------------------------------------------------
#define FST 72
#define QBUF  (128 * FST * 2)     // 18432
#define KVBUF (64 * FST * 2)      // 9216
#define KVSTAGE (2 * KVBUF)       // 18432
#define FSMEM (QBUF + 2 * KVSTAGE)   // 55296

__device__ __forceinline__ void f_loadKV(unsigned kvbase, int stage, int jt,
                                         const __half* Kf, const __half* Vf, int tid)
{
    const int row = tid >> 2;
    const int c2  = tid & 3;
    const unsigned dst0 = kvbase + (unsigned)(stage * KVSTAGE + row * 144 + c2 * 32);
    const size_t src = (size_t)(jt + row) * Dmodel + c2 * 16;
    cpa16(dst0,              Kf + src);
    cpa16(dst0 + 16,         Kf + src + 8);
    cpa16(dst0 + KVBUF,      Vf + src);
    cpa16(dst0 + KVBUF + 16, Vf + src + 8);
}

__global__ __launch_bounds__(256, 2) void flash_attn()
{
    extern __shared__ __align__(16) char smf[];
    const unsigned sbase  = smem_u32(smf);
    const unsigned kvbase = sbase + QBUF;

    const int tid  = threadIdx.x;
    const int wid  = tid >> 5;
    const int lane = tid & 31;
    const int tg   = lane & 3;
    const int bh   = blockIdx.y;
    const int b    = bh >> 4;
    const int h    = bh & 15;
    const int q0   = blockIdx.x * 128;

    const size_t hoff = (size_t)b * Nseq * Dmodel + h * DKh;
    const __half* Qf = g_pf + hoff;
    const __half* Kf = g_pf + NELEM + hoff;
    const __half* Vf = g_pf + 2 * NELEM + hoff;

    // prologue
    {
        const int row = tid >> 1;
        const int c4  = tid & 1;
        const unsigned dq = sbase + (unsigned)(row * 144 + c4 * 64);
        const size_t src = (size_t)(q0 + row) * Dmodel + c4 * 32;
#pragma unroll
        for (int j = 0; j < 4; j++)
            cpa16(dq + j * 16, Qf + src + j * 8);
    }
    f_loadKV(kvbase, 0, 0, Kf, Vf, tid);
    cpa_commit();
    f_loadKV(kvbase, 1, 64, Kf, Vf, tid);
    cpa_commit();
    cpa_wait<1>();
    __syncthreads();

    // persistent Q fragments (single fp16)
    const unsigned qa = sbase +
        (unsigned)(((wid * 16 + (lane & 15)) * FST + (lane >> 4) * 8) * 2);
    unsigned aq[4][4];
#pragma unroll
    for (int ks = 0; ks < 4; ks++)
        ldsm_x4(aq[ks][0], aq[ks][1], aq[ks][2], aq[ks][3], qa + ks * 32);

    const unsigned kb_off = (unsigned)(((lane & 15) * FST + (lane >> 4) * 8) * 2);

    float oacc[8][4];
#pragma unroll
    for (int nt = 0; nt < 8; nt++)
#pragma unroll
        for (int i = 0; i < 4; i++) oacc[nt][i] = 0.0f;
    float mr0 = -1e30f, mr1 = -1e30f, lr0 = 0.0f, lr1 = 0.0f;

    const int NT = Nseq / 64;   // 32
    for (int jt = 0; jt < NT; jt++) {
        const unsigned st = kvbase + (unsigned)((jt & 1) * KVSTAGE);
        const unsigned kb = st + kb_off;
        const unsigned vb = st + KVBUF + kb_off;

        // ---- S = Q K^T (logits: scale pre-folded into Q) ----
        float sacc[8][4];
#pragma unroll
        for (int nt = 0; nt < 8; nt++)
#pragma unroll
            for (int i = 0; i < 4; i++) sacc[nt][i] = 0.0f;

#pragma unroll
        for (int ks = 0; ks < 4; ks++) {
#pragma unroll
            for (int jb = 0; jb < 4; jb++) {
                unsigned r0, r1, r2, r3;
                ldsm_x4(r0, r1, r2, r3,
                        kb + (unsigned)((jb * 16 * FST + ks * 16) * 2));
                unsigned bf0[2] = {r0, r2};
                unsigned bf1[2] = {r1, r3};
                mma16816h(sacc[jb * 2 + 0], aq[ks], bf0);
                mma16816h(sacc[jb * 2 + 1], aq[ks], bf1);
            }
        }

        // ---- online softmax ----
        float mx0 = -1e30f, mx1 = -1e30f;
#pragma unroll
        for (int nt = 0; nt < 8; nt++) {
            mx0 = fmaxf(mx0, fmaxf(sacc[nt][0], sacc[nt][1]));
            mx1 = fmaxf(mx1, fmaxf(sacc[nt][2], sacc[nt][3]));
        }
        mx0 = fmaxf(mx0, __shfl_xor_sync(0xffffffffu, mx0, 1));
        mx0 = fmaxf(mx0, __shfl_xor_sync(0xffffffffu, mx0, 2));
        mx1 = fmaxf(mx1, __shfl_xor_sync(0xffffffffu, mx1, 1));
        mx1 = fmaxf(mx1, __shfl_xor_sync(0xffffffffu, mx1, 2));
        const float mn0 = fmaxf(mr0, mx0);
        const float mn1 = fmaxf(mr1, mx1);
        const float al0 = __expf(mr0 - mn0);
        const float al1 = __expf(mr1 - mn1);

        unsigned pa[4][4];
        float rs0 = 0.0f, rs1 = 0.0f;
#pragma unroll
        for (int nt = 0; nt < 8; nt++) {
            const float p0 = __expf(sacc[nt][0] - mn0);
            const float p1 = __expf(sacc[nt][1] - mn0);
            const float p2 = __expf(sacc[nt][2] - mn1);
            const float p3 = __expf(sacc[nt][3] - mn1);
            rs0 += p0 + p1;
            rs1 += p2 + p3;
            const unsigned h01 = packf16(p0, p1);
            const unsigned h23 = packf16(p2, p3);
            const int t = nt >> 1;
            if ((nt & 1) == 0) { pa[t][0] = h01; pa[t][1] = h23; }
            else               { pa[t][2] = h01; pa[t][3] = h23; }
            oacc[nt][0] *= al0; oacc[nt][1] *= al0;
            oacc[nt][2] *= al1; oacc[nt][3] *= al1;
        }
        rs0 += __shfl_xor_sync(0xffffffffu, rs0, 1);
        rs0 += __shfl_xor_sync(0xffffffffu, rs0, 2);
        rs1 += __shfl_xor_sync(0xffffffffu, rs1, 1);
        rs1 += __shfl_xor_sync(0xffffffffu, rs1, 2);
        lr0 = lr0 * al0 + rs0;
        lr1 = lr1 * al1 + rs1;
        mr0 = mn0; mr1 = mn1;

        // ---- O += P V (fp16 single-pass) ----
#pragma unroll
        for (int t = 0; t < 4; t++) {
#pragma unroll
            for (int db = 0; db < 4; db++) {
                unsigned r0, r1, r2, r3;
                ldsm_x4_t(r0, r1, r2, r3,
                          vb + (unsigned)((t * 16 * FST + db * 16) * 2));
                unsigned b0[2] = {r0, r1};
                unsigned b1[2] = {r2, r3};
                mma16816h(oacc[db * 2 + 0], pa[t], b0);
                mma16816h(oacc[db * 2 + 1], pa[t], b1);
            }
        }

        __syncthreads();
        if (jt + 1 < NT) {
            if (jt + 2 < NT) {
                f_loadKV(kvbase, jt & 1, (jt + 2) * 64, Kf, Vf, tid);
                cpa_commit();
                cpa_wait<1>();
            } else {
                cpa_wait<0>();
            }
            __syncthreads();
        }
    }

    // ---- epilogue: write attention out in split bf16 form ----
    const float inv0 = 1.0f / lr0;
    const float inv1 = 1.0f / lr1;
    __nv_bfloat16* Ch = g_Ch + hoff;
    __nv_bfloat16* Cl = g_Cl + hoff;
    const int row0 = q0 + wid * 16 + (lane >> 2);
#pragma unroll
    for (int nt = 0; nt < 8; nt++) {
        const int d = nt * 8 + tg * 2;
        unsigned h2, l2;
        pack_hilo(oacc[nt][0] * inv0, oacc[nt][1] * inv0, h2, l2);
        *(unsigned*)(Ch + (size_t)row0 * Dmodel + d) = h2;
        *(unsigned*)(Cl + (size_t)row0 * Dmodel + d) = l2;
        pack_hilo(oacc[nt][2] * inv1, oacc[nt][3] * inv1, h2, l2);
        *(unsigned*)(Ch + (size_t)(row0 + 8) * Dmodel + d) = h2;
        *(unsigned*)(Cl + (size_t)(row0 + 8) * Dmodel + d) = l2;
    }
}

// ---------------------------------------------------------------------------
extern "C" void kernel_launch(void* const* d_in, const int* in_sizes, int n_in,
                              void* d_out, int out_size)
{
    const float* q  = (const float*)d_in[0];
    const float* k  = (const float*)d_in[1];
    const float* v  = (const float*)d_in[2];
    const float* Wq = (const float*)d_in[3];
    const float* bq = (const float*)d_in[4];
    const float* Wk = (const float*)d_in[5];
    const float* bk = (const float*)d_in[6];
    const float* Wv = (const float*)d_in[7];
    const float* bv = (const float*)d_in[8];
    const float* Wo = (const float*)d_in[9];
    const float* bo = (const float*)d_in[10];
    float* out = (float*)d_out;

    cudaFuncSetAttribute(flash_attn, cudaFuncAttributeMaxDynamicSharedMemorySize, FSMEM);
    cudaFuncSetAttribute(qkv_gemm, cudaFuncAttributeMaxDynamicSharedMemorySize, GSMEM);
    cudaFuncSetAttribute(out_gemm, cudaFuncAttributeMaxDynamicSharedMemorySize, GSMEM);

    split_inputs<<<dim3(NELEM / 1024, 1, 3), 256>>>(q, k, v);
    split_weights<<<dim3(WELEM / 1024, 1, 4), 256>>>(Wq, Wk, Wv, Wo);

    dim3 gqkv(Dmodel / 128, Mrows / 128, 3);   // 8 x 32 x 3
    qkv_gemm<<<gqkv, 256, GSMEM>>>(bq, bk, bv);

    dim3 gf(Nseq / 128, Bsz * Hh);             // 16 x 32
    flash_attn<<<gf, 256, FSMEM>>>();

    dim3 go(Dmodel / 128, Mrows / 128);        // 8 x 32
    out_gemm<<<go, 256, GSMEM>>>(bo, out);
}

// round 9
// speedup vs baseline: 5.5113x; 1.6481x over previous
#include <cuda_runtime.h>
#include <cuda_fp16.h>

// Problem constants
#define Bsz    2
#define Nseq   2048
#define Dmodel 1024
#define Hh     16
#define DKh    64
#define Mrows  4096
#define NELEM  (Mrows * Dmodel)     // 4,194,304
#define WELEM  (Dmodel * Dmodel)    // 1,048,576
#define SCALE  0.125f

// ---- mma.sync / ldmatrix / cp.async helpers (base sm_80+ ISA) ----
__device__ __forceinline__ unsigned smem_u32(const void* p) {
    unsigned a;
    asm("{ .reg .u64 t; cvta.to.shared.u64 t, %1; cvt.u32.u64 %0, t; }" : "=r"(a) : "l"(p));
    return a;
}
__device__ __forceinline__ void ldsm_x4(unsigned& r0, unsigned& r1, unsigned& r2, unsigned& r3,
                                        unsigned addr) {
    asm volatile("ldmatrix.sync.aligned.m8n8.x4.shared.b16 {%0,%1,%2,%3}, [%4];"
                 : "=r"(r0), "=r"(r1), "=r"(r2), "=r"(r3) : "r"(addr));
}
__device__ __forceinline__ void ldsm_x4_t(unsigned& r0, unsigned& r1, unsigned& r2, unsigned& r3,
                                          unsigned addr) {
    asm volatile("ldmatrix.sync.aligned.m8n8.x4.trans.shared.b16 {%0,%1,%2,%3}, [%4];"
                 : "=r"(r0), "=r"(r1), "=r"(r2), "=r"(r3) : "r"(addr));
}
__device__ __forceinline__ void mma16816h(float* c, const unsigned* a, const unsigned* b) {
    asm volatile("mma.sync.aligned.m16n8k16.row.col.f32.f16.f16.f32 "
                 "{%0,%1,%2,%3},{%4,%5,%6,%7},{%8,%9},{%0,%1,%2,%3};"
                 : "+f"(c[0]), "+f"(c[1]), "+f"(c[2]), "+f"(c[3])
                 : "r"(a[0]), "r"(a[1]), "r"(a[2]), "r"(a[3]), "r"(b[0]), "r"(b[1]));
}
__device__ __forceinline__ void cpa16(unsigned dst, const void* src) {
    asm volatile("cp.async.cg.shared.global [%0], [%1], 16;" :: "r"(dst), "l"(src));
}
__device__ __forceinline__ void cpa_commit() { asm volatile("cp.async.commit_group;"); }
template<int N> __device__ __forceinline__ void cpa_wait() {
    asm volatile("cp.async.wait_group %0;" :: "n"(N));
}
__device__ __forceinline__ unsigned packf16(float x, float y) {
    __half2 t = __floats2half2_rn(x, y);
    return *reinterpret_cast<unsigned*>(&t);
}

// ---- scratch (fp16) ----
__device__ __half g_xf[3 * NELEM];   // converted inputs q,k,v
__device__ __half g_wf[4 * WELEM];   // converted weights Wq,Wk,Wv,Wo
__device__ __half g_pf[3 * NELEM];   // projected Q(pre-scaled),K,V
__device__ __half g_Cf[NELEM];       // attention output

// ---------------------------------------------------------------------------
// Convert kernels: fp32 -> fp16
// ---------------------------------------------------------------------------
__global__ __launch_bounds__(256) void conv_inputs(const float* __restrict__ q,
                                                   const float* __restrict__ k,
                                                   const float* __restrict__ v)
{
    const int z = blockIdx.z;
    const float* src = (z == 0) ? q : (z == 1) ? k : v;
    __half* dst = g_xf + (size_t)z * NELEM;
    const size_t i = ((size_t)blockIdx.x * 256 + threadIdx.x) * 4;
    float4 f = *(const float4*)(src + i);
    uint2 o;
    o.x = packf16(f.x, f.y);
    o.y = packf16(f.z, f.w);
    *(uint2*)(dst + i) = o;
}

__global__ __launch_bounds__(256) void conv_weights(const float* __restrict__ wq,
                                                    const float* __restrict__ wk,
                                                    const float* __restrict__ wv,
                                                    const float* __restrict__ wo)
{
    const int z = blockIdx.z;
    const float* src = (z == 0) ? wq : (z == 1) ? wk : (z == 2) ? wv : wo;
    __half* dst = g_wf + (size_t)z * WELEM;
    const size_t i = ((size_t)blockIdx.x * 256 + threadIdx.x) * 4;
    float4 f = *(const float4*)(src + i);
    uint2 o;
    o.x = packf16(f.x, f.y);
    o.y = packf16(f.z, f.w);
    *(uint2*)(dst + i) = o;
}

// ---------------------------------------------------------------------------
// fp16 single-pass HMMA GEMM, cp.async 2-stage: C = X @ W^T + bias
// Tile 128x128, Kc=64, 8 warps (2x4), warp tile 64x32.
// smem/stage: Af|Bf each [128][72] fp16 (stride 144 B, ldsm conflict-free).
// ---------------------------------------------------------------------------
#define KC 64
#define NCH (Dmodel / KC)     // 16
#define GST 72
#define GBUF (128 * GST * 2)  // 18432 B
#define GSTAGE (2 * GBUF)     // 36864 B
#define GSMEM (2 * GSTAGE)    // 73728 B

__device__ __forceinline__ void g_load(unsigned sbase, int stage,
                                       const __half* Xf, const __half* Wf,
                                       int m0, int n0, int k0, int tid)
{
    const int row = tid >> 1;
    const int co  = (tid & 1) * 32;              // element offset within chunk
    const unsigned dst0 = sbase + (unsigned)(stage * GSTAGE + row * 144 + (tid & 1) * 64);
    const size_t asrc = (size_t)(m0 + row) * Dmodel + k0 + co;
    const size_t bsrc = (size_t)(n0 + row) * Dmodel + k0 + co;
#pragma unroll
    for (int j = 0; j < 4; j++) {
        cpa16(dst0 + j * 16,        Xf + asrc + j * 8);
        cpa16(dst0 + GBUF + j * 16, Wf + bsrc + j * 8);
    }
}

__device__ __forceinline__ void gemm_body(const __half* __restrict__ Xf,
                                          const __half* __restrict__ Wf,
                                          const float* __restrict__ bias,
                                          __half* C16, float* Cf, float cscale)
{
    extern __shared__ __align__(16) char smg[];
    const unsigned sbase = smem_u32(smg);

    const int tid  = threadIdx.x;
    const int wid  = tid >> 5;
    const int lane = tid & 31;
    const int wm   = wid >> 2;
    const int wn   = wid & 3;
    const int m0   = blockIdx.y * 128;
    const int n0   = blockIdx.x * 128;

    float acc[4][4][4];
#pragma unroll
    for (int mt = 0; mt < 4; mt++)
#pragma unroll
        for (int nt = 0; nt < 4; nt++)
#pragma unroll
            for (int i = 0; i < 4; i++) acc[mt][nt][i] = 0.0f;

    const unsigned a_off = (unsigned)(((wm * 64 + (lane & 15)) * GST + (lane >> 4) * 8) * 2);
    const unsigned b_off = (unsigned)(((wn * 32 + (lane & 15)) * GST + (lane >> 4) * 8) * 2);

    g_load(sbase, 0, Xf, Wf, m0, n0, 0, tid);
    cpa_commit();
    g_load(sbase, 1, Xf, Wf, m0, n0, KC, tid);
    cpa_commit();
    cpa_wait<1>();
    __syncthreads();

    for (int ch = 0; ch < NCH; ch++) {
        const unsigned st = sbase + (unsigned)((ch & 1) * GSTAGE);
        const unsigned abase = st + a_off;
        const unsigned bbase = st + GBUF + b_off;

#pragma unroll
        for (int ks = 0; ks < 4; ks++) {
            const unsigned koff = (unsigned)(ks * 16 * 2);
            unsigned af[4][4];
#pragma unroll
            for (int mt = 0; mt < 4; mt++)
                ldsm_x4(af[mt][0], af[mt][1], af[mt][2], af[mt][3],
                        abase + koff + (unsigned)(mt * 16 * GST * 2));
            unsigned bf[4][2];
#pragma unroll
            for (int np = 0; np < 2; np++) {
                unsigned r0, r1, r2, r3;
                ldsm_x4(r0, r1, r2, r3,
                        bbase + koff + (unsigned)(np * 16 * GST * 2));
                bf[np * 2 + 0][0] = r0; bf[np * 2 + 0][1] = r2;
                bf[np * 2 + 1][0] = r1; bf[np * 2 + 1][1] = r3;
            }
#pragma unroll
            for (int mt = 0; mt < 4; mt++)
#pragma unroll
                for (int nt = 0; nt < 4; nt++)
                    mma16816h(acc[mt][nt], af[mt], bf[nt]);
        }
        __syncthreads();

        if (ch + 1 < NCH) {
            if (ch + 2 < NCH) {
                g_load(sbase, ch & 1, Xf, Wf, m0, n0, (ch + 2) * KC, tid);
                cpa_commit();
                cpa_wait<1>();
            } else {
                cpa_wait<0>();
            }
            __syncthreads();
        }
    }

    const int g   = lane >> 2;
    const int tig = lane & 3;
#pragma unroll
    for (int mt = 0; mt < 4; mt++) {
        const int r0 = m0 + wm * 64 + mt * 16 + g;
#pragma unroll
        for (int nt = 0; nt < 4; nt++) {
            const int cidx = n0 + wn * 32 + nt * 8 + tig * 2;
            const float2 bv = *(const float2*)(bias + cidx);
            const float x0 = acc[mt][nt][0] + bv.x;
            const float x1 = acc[mt][nt][1] + bv.y;
            const float x2 = acc[mt][nt][2] + bv.x;
            const float x3 = acc[mt][nt][3] + bv.y;
            if (Cf) {
                *(float2*)(Cf + (size_t)r0 * Dmodel + cidx) = make_float2(x0, x1);
                *(float2*)(Cf + (size_t)(r0 + 8) * Dmodel + cidx) = make_float2(x2, x3);
            } else {
                *(unsigned*)(C16 + (size_t)r0 * Dmodel + cidx) =
                    packf16(x0 * cscale, x1 * cscale);
                *(unsigned*)(C16 + (size_t)(r0 + 8) * Dmodel + cidx) =
                    packf16(x2 * cscale, x3 * cscale);
            }
        }
    }
}

__global__ __launch_bounds__(256, 2) void qkv_gemm(const float* __restrict__ bq,
                                                   const float* __restrict__ bk,
                                                   const float* __restrict__ bv)
{
    const int z = blockIdx.z;
    const float* bias = (z == 0) ? bq : (z == 1) ? bk : bv;
    const float cs = (z == 0) ? SCALE : 1.0f;   // fold softmax scale into Q
    gemm_body(g_xf + (size_t)z * NELEM, g_wf + (size_t)z * WELEM,
              bias, g_pf + (size_t)z * NELEM, nullptr, cs);
}

__global__ __launch_bounds__(256, 2) void out_gemm(const float* __restrict__ bo,
                                                   float* __restrict__ out)
{
    gemm_body(g_Cf, g_wf + (size_t)3 * WELEM, bo, nullptr, out, 1.0f);
}

// ---------------------------------------------------------------------------
// Flash attention, fp16 single-pass HMMA, cp.async 2-stage K/V pipeline.
// CTA: 128 q-rows x (b,h); 8 warps x 16 rows; j-tiles of 64.
// smem: Qf [128][72] + 2 stages of (Kf|Vf [64][72]) fp16.
// ---------------------------------------------------------------------------
#define FST 72
#define QBUF  (128 * FST * 2)     // 18432
#define KVBUF (64 * FST * 2)      // 9216
#define KVSTAGE (2 * KVBUF)       // 18432
#define FSMEM (QBUF + 2 * KVSTAGE)   // 55296

__device__ __forceinline__ void f_loadKV(unsigned kvbase, int stage, int jt,
                                         const __half* Kf, const __half* Vf, int tid)
{
    const int row = tid >> 2;
    const int c2  = tid & 3;
    const unsigned dst0 = kvbase + (unsigned)(stage * KVSTAGE + row * 144 + c2 * 32);
    const size_t src = (size_t)(jt + row) * Dmodel + c2 * 16;
    cpa16(dst0,              Kf + src);
    cpa16(dst0 + 16,         Kf + src + 8);
    cpa16(dst0 + KVBUF,      Vf + src);
    cpa16(dst0 + KVBUF + 16, Vf + src + 8);
}

__global__ __launch_bounds__(256, 2) void flash_attn()
{
    extern __shared__ __align__(16) char smf[];
    const unsigned sbase  = smem_u32(smf);
    const unsigned kvbase = sbase + QBUF;

    const int tid  = threadIdx.x;
    const int wid  = tid >> 5;
    const int lane = tid & 31;
    const int tg   = lane & 3;
    const int bh   = blockIdx.y;
    const int b    = bh >> 4;
    const int h    = bh & 15;
    const int q0   = blockIdx.x * 128;

    const size_t hoff = (size_t)b * Nseq * Dmodel + h * DKh;
    const __half* Qf = g_pf + hoff;
    const __half* Kf = g_pf + NELEM + hoff;
    const __half* Vf = g_pf + 2 * NELEM + hoff;

    // prologue
    {
        const int row = tid >> 1;
        const int c4  = tid & 1;
        const unsigned dq = sbase + (unsigned)(row * 144 + c4 * 64);
        const size_t src = (size_t)(q0 + row) * Dmodel + c4 * 32;
#pragma unroll
        for (int j = 0; j < 4; j++)
            cpa16(dq + j * 16, Qf + src + j * 8);
    }
    f_loadKV(kvbase, 0, 0, Kf, Vf, tid);
    cpa_commit();
    f_loadKV(kvbase, 1, 64, Kf, Vf, tid);
    cpa_commit();
    cpa_wait<1>();
    __syncthreads();

    // persistent Q fragments
    const unsigned qa = sbase +
        (unsigned)(((wid * 16 + (lane & 15)) * FST + (lane >> 4) * 8) * 2);
    unsigned aq[4][4];
#pragma unroll
    for (int ks = 0; ks < 4; ks++)
        ldsm_x4(aq[ks][0], aq[ks][1], aq[ks][2], aq[ks][3], qa + ks * 32);

    const unsigned kb_off = (unsigned)(((lane & 15) * FST + (lane >> 4) * 8) * 2);

    float oacc[8][4];
#pragma unroll
    for (int nt = 0; nt < 8; nt++)
#pragma unroll
        for (int i = 0; i < 4; i++) oacc[nt][i] = 0.0f;
    float mr0 = -1e30f, mr1 = -1e30f, lr0 = 0.0f, lr1 = 0.0f;

    const int NT = Nseq / 64;   // 32
    for (int jt = 0; jt < NT; jt++) {
        const unsigned st = kvbase + (unsigned)((jt & 1) * KVSTAGE);
        const unsigned kb = st + kb_off;
        const unsigned vb = st + KVBUF + kb_off;

        // ---- S = Q K^T (scale pre-folded into Q) ----
        float sacc[8][4];
#pragma unroll
        for (int nt = 0; nt < 8; nt++)
#pragma unroll
            for (int i = 0; i < 4; i++) sacc[nt][i] = 0.0f;

#pragma unroll
        for (int ks = 0; ks < 4; ks++) {
#pragma unroll
            for (int jb = 0; jb < 4; jb++) {
                unsigned r0, r1, r2, r3;
                ldsm_x4(r0, r1, r2, r3,
                        kb + (unsigned)((jb * 16 * FST + ks * 16) * 2));
                unsigned bf0[2] = {r0, r2};
                unsigned bf1[2] = {r1, r3};
                mma16816h(sacc[jb * 2 + 0], aq[ks], bf0);
                mma16816h(sacc[jb * 2 + 1], aq[ks], bf1);
            }
        }

        // ---- online softmax ----
        float mx0 = -1e30f, mx1 = -1e30f;
#pragma unroll
        for (int nt = 0; nt < 8; nt++) {
            mx0 = fmaxf(mx0, fmaxf(sacc[nt][0], sacc[nt][1]));
            mx1 = fmaxf(mx1, fmaxf(sacc[nt][2], sacc[nt][3]));
        }
        mx0 = fmaxf(mx0, __shfl_xor_sync(0xffffffffu, mx0, 1));
        mx0 = fmaxf(mx0, __shfl_xor_sync(0xffffffffu, mx0, 2));
        mx1 = fmaxf(mx1, __shfl_xor_sync(0xffffffffu, mx1, 1));
        mx1 = fmaxf(mx1, __shfl_xor_sync(0xffffffffu, mx1, 2));
        const float mn0 = fmaxf(mr0, mx0);
        const float mn1 = fmaxf(mr1, mx1);
        const float al0 = __expf(mr0 - mn0);
        const float al1 = __expf(mr1 - mn1);

        unsigned pa[4][4];
        float rs0 = 0.0f, rs1 = 0.0f;
#pragma unroll
        for (int nt = 0; nt < 8; nt++) {
            const float p0 = __expf(sacc[nt][0] - mn0);
            const float p1 = __expf(sacc[nt][1] - mn0);
            const float p2 = __expf(sacc[nt][2] - mn1);
            const float p3 = __expf(sacc[nt][3] - mn1);
            rs0 += p0 + p1;
            rs1 += p2 + p3;
            const unsigned h01 = packf16(p0, p1);
            const unsigned h23 = packf16(p2, p3);
            const int t = nt >> 1;
            if ((nt & 1) == 0) { pa[t][0] = h01; pa[t][1] = h23; }
            else               { pa[t][2] = h01; pa[t][3] = h23; }
            oacc[nt][0] *= al0; oacc[nt][1] *= al0;
            oacc[nt][2] *= al1; oacc[nt][3] *= al1;
        }
        rs0 += __shfl_xor_sync(0xffffffffu, rs0, 1);
        rs0 += __shfl_xor_sync(0xffffffffu, rs0, 2);
        rs1 += __shfl_xor_sync(0xffffffffu, rs1, 1);
        rs1 += __shfl_xor_sync(0xffffffffu, rs1, 2);
        lr0 = lr0 * al0 + rs0;
        lr1 = lr1 * al1 + rs1;
        mr0 = mn0; mr1 = mn1;

        // ---- O += P V ----
#pragma unroll
        for (int t = 0; t < 4; t++) {
#pragma unroll
            for (int db = 0; db < 4; db++) {
                unsigned r0, r1, r2, r3;
                ldsm_x4_t(r0, r1, r2, r3,
                          vb + (unsigned)((t * 16 * FST + db * 16) * 2));
                unsigned b0[2] = {r0, r1};
                unsigned b1[2] = {r2, r3};
                mma16816h(oacc[db * 2 + 0], pa[t], b0);
                mma16816h(oacc[db * 2 + 1], pa[t], b1);
            }
        }

        __syncthreads();
        if (jt + 1 < NT) {
            if (jt + 2 < NT) {
                f_loadKV(kvbase, jt & 1, (jt + 2) * 64, Kf, Vf, tid);
                cpa_commit();
                cpa_wait<1>();
            } else {
                cpa_wait<0>();
            }
            __syncthreads();
        }
    }

    // ---- epilogue: write attention out as fp16 ----
    const float inv0 = 1.0f / lr0;
    const float inv1 = 1.0f / lr1;
    __half* Ch = g_Cf + hoff;
    const int row0 = q0 + wid * 16 + (lane >> 2);
#pragma unroll
    for (int nt = 0; nt < 8; nt++) {
        const int d = nt * 8 + tg * 2;
        *(unsigned*)(Ch + (size_t)row0 * Dmodel + d) =
            packf16(oacc[nt][0] * inv0, oacc[nt][1] * inv0);
        *(unsigned*)(Ch + (size_t)(row0 + 8) * Dmodel + d) =
            packf16(oacc[nt][2] * inv1, oacc[nt][3] * inv1);
    }
}

// ---------------------------------------------------------------------------
extern "C" void kernel_launch(void* const* d_in, const int* in_sizes, int n_in,
                              void* d_out, int out_size)
{
    const float* q  = (const float*)d_in[0];
    const float* k  = (const float*)d_in[1];
    const float* v  = (const float*)d_in[2];
    const float* Wq = (const float*)d_in[3];
    const float* bq = (const float*)d_in[4];
    const float* Wk = (const float*)d_in[5];
    const float* bk = (const float*)d_in[6];
    const float* Wv = (const float*)d_in[7];
    const float* bv = (const float*)d_in[8];
    const float* Wo = (const float*)d_in[9];
    const float* bo = (const float*)d_in[10];
    float* out = (float*)d_out;

    cudaFuncSetAttribute(flash_attn, cudaFuncAttributeMaxDynamicSharedMemorySize, FSMEM);
    cudaFuncSetAttribute(qkv_gemm, cudaFuncAttributeMaxDynamicSharedMemorySize, GSMEM);
    cudaFuncSetAttribute(out_gemm, cudaFuncAttributeMaxDynamicSharedMemorySize, GSMEM);

    conv_inputs<<<dim3(NELEM / 1024, 1, 3), 256>>>(q, k, v);
    conv_weights<<<dim3(WELEM / 1024, 1, 4), 256>>>(Wq, Wk, Wv, Wo);

    dim3 gqkv(Dmodel / 128, Mrows / 128, 3);   // 8 x 32 x 3
    qkv_gemm<<<gqkv, 256, GSMEM>>>(bq, bk, bv);

    dim3 gf(Nseq / 128, Bsz * Hh);             // 16 x 32
    flash_attn<<<gf, 256, FSMEM>>>();

    dim3 go(Dmodel / 128, Mrows / 128);        // 8 x 32
    out_gemm<<<go, 256, GSMEM>>>(bo, out);
}

// round 10
// speedup vs baseline: 5.5681x; 1.0103x over previous
#include <cuda_runtime.h>
#include <cuda_fp16.h>

// Problem constants
#define Bsz    2
#define Nseq   2048
#define Dmodel 1024
#define Hh     16
#define DKh    64
#define Mrows  4096
#define NELEM  (Mrows * Dmodel)     // 4,194,304
#define WELEM  (Dmodel * Dmodel)    // 1,048,576
#define SCALE  0.125f
#define QSCALE (0.125f * 1.44269504088896f)   // fold log2(e): softmax in exp2 domain

// ---- mma.sync / ldmatrix / cp.async helpers (base sm_80+ ISA) ----
__device__ __forceinline__ unsigned smem_u32(const void* p) {
    unsigned a;
    asm("{ .reg .u64 t; cvta.to.shared.u64 t, %1; cvt.u32.u64 %0, t; }" : "=r"(a) : "l"(p));
    return a;
}
__device__ __forceinline__ void ldsm_x4(unsigned& r0, unsigned& r1, unsigned& r2, unsigned& r3,
                                        unsigned addr) {
    asm volatile("ldmatrix.sync.aligned.m8n8.x4.shared.b16 {%0,%1,%2,%3}, [%4];"
                 : "=r"(r0), "=r"(r1), "=r"(r2), "=r"(r3) : "r"(addr));
}
__device__ __forceinline__ void ldsm_x4_t(unsigned& r0, unsigned& r1, unsigned& r2, unsigned& r3,
                                          unsigned addr) {
    asm volatile("ldmatrix.sync.aligned.m8n8.x4.trans.shared.b16 {%0,%1,%2,%3}, [%4];"
                 : "=r"(r0), "=r"(r1), "=r"(r2), "=r"(r3) : "r"(addr));
}
__device__ __forceinline__ void mma16816h(float* c, const unsigned* a, const unsigned* b) {
    asm volatile("mma.sync.aligned.m16n8k16.row.col.f32.f16.f16.f32 "
                 "{%0,%1,%2,%3},{%4,%5,%6,%7},{%8,%9},{%0,%1,%2,%3};"
                 : "+f"(c[0]), "+f"(c[1]), "+f"(c[2]), "+f"(c[3])
                 : "r"(a[0]), "r"(a[1]), "r"(a[2]), "r"(a[3]), "r"(b[0]), "r"(b[1]));
}
__device__ __forceinline__ void cpa16(unsigned dst, const void* src) {
    asm volatile("cp.async.cg.shared.global [%0], [%1], 16;" :: "r"(dst), "l"(src));
}
__device__ __forceinline__ void cpa_commit() { asm volatile("cp.async.commit_group;"); }
template<int N> __device__ __forceinline__ void cpa_wait() {
    asm volatile("cp.async.wait_group %0;" :: "n"(N));
}
__device__ __forceinline__ unsigned packf16(float x, float y) {
    __half2 t = __floats2half2_rn(x, y);
    return *reinterpret_cast<unsigned*>(&t);
}

// ---- scratch (fp16) ----
__device__ __half g_xf[3 * NELEM];   // converted inputs q,k,v
__device__ __half g_wf[4 * WELEM];   // converted weights Wq,Wk,Wv,Wo
__device__ __half g_pf[3 * NELEM];   // projected Q(pre-scaled),K,V
__device__ __half g_Cf[NELEM];       // attention output

// ---------------------------------------------------------------------------
// Convert kernels: fp32 -> fp16
// ---------------------------------------------------------------------------
__global__ __launch_bounds__(256) void conv_inputs(const float* __restrict__ q,
                                                   const float* __restrict__ k,
                                                   const float* __restrict__ v)
{
    const int z = blockIdx.z;
    const float* src = (z == 0) ? q : (z == 1) ? k : v;
    __half* dst = g_xf + (size_t)z * NELEM;
    const size_t i = ((size_t)blockIdx.x * 256 + threadIdx.x) * 4;
    float4 f = *(const float4*)(src + i);
    uint2 o;
    o.x = packf16(f.x, f.y);
    o.y = packf16(f.z, f.w);
    *(uint2*)(dst + i) = o;
}

__global__ __launch_bounds__(256) void conv_weights(const float* __restrict__ wq,
                                                    const float* __restrict__ wk,
                                                    const float* __restrict__ wv,
                                                    const float* __restrict__ wo)
{
    const int z = blockIdx.z;
    const float* src = (z == 0) ? wq : (z == 1) ? wk : (z == 2) ? wv : wo;
    __half* dst = g_wf + (size_t)z * WELEM;
    const size_t i = ((size_t)blockIdx.x * 256 + threadIdx.x) * 4;
    float4 f = *(const float4*)(src + i);
    uint2 o;
    o.x = packf16(f.x, f.y);
    o.y = packf16(f.z, f.w);
    *(uint2*)(dst + i) = o;
}

// ---------------------------------------------------------------------------
// fp16 single-pass HMMA GEMM, cp.async 2-stage: C = X @ W^T + bias
// Tile 128x128, Kc=64, 8 warps (2x4), warp tile 64x32.
// ---------------------------------------------------------------------------
#define KC 64
#define NCH (Dmodel / KC)     // 16
#define GST 72
#define GBUF (128 * GST * 2)  // 18432 B
#define GSTAGE (2 * GBUF)     // 36864 B
#define GSMEM (2 * GSTAGE)    // 73728 B

__device__ __forceinline__ void g_load(unsigned sbase, int stage,
                                       const __half* Xf, const __half* Wf,
                                       int m0, int n0, int k0, int tid)
{
    const int row = tid >> 1;
    const int co  = (tid & 1) * 32;
    const unsigned dst0 = sbase + (unsigned)(stage * GSTAGE + row * 144 + (tid & 1) * 64);
    const size_t asrc = (size_t)(m0 + row) * Dmodel + k0 + co;
    const size_t bsrc = (size_t)(n0 + row) * Dmodel + k0 + co;
#pragma unroll
    for (int j = 0; j < 4; j++) {
        cpa16(dst0 + j * 16,        Xf + asrc + j * 8);
        cpa16(dst0 + GBUF + j * 16, Wf + bsrc + j * 8);
    }
}

__device__ __forceinline__ void gemm_body(const __half* __restrict__ Xf,
                                          const __half* __restrict__ Wf,
                                          const float* __restrict__ bias,
                                          __half* C16, float* Cf, float cscale)
{
    extern __shared__ __align__(16) char smg[];
    const unsigned sbase = smem_u32(smg);

    const int tid  = threadIdx.x;
    const int wid  = tid >> 5;
    const int lane = tid & 31;
    const int wm   = wid >> 2;
    const int wn   = wid & 3;
    const int m0   = blockIdx.y * 128;
    const int n0   = blockIdx.x * 128;

    float acc[4][4][4];
#pragma unroll
    for (int mt = 0; mt < 4; mt++)
#pragma unroll
        for (int nt = 0; nt < 4; nt++)
#pragma unroll
            for (int i = 0; i < 4; i++) acc[mt][nt][i] = 0.0f;

    const unsigned a_off = (unsigned)(((wm * 64 + (lane & 15)) * GST + (lane >> 4) * 8) * 2);
    const unsigned b_off = (unsigned)(((wn * 32 + (lane & 15)) * GST + (lane >> 4) * 8) * 2);

    g_load(sbase, 0, Xf, Wf, m0, n0, 0, tid);
    cpa_commit();
    g_load(sbase, 1, Xf, Wf, m0, n0, KC, tid);
    cpa_commit();
    cpa_wait<1>();
    __syncthreads();

    for (int ch = 0; ch < NCH; ch++) {
        const unsigned st = sbase + (unsigned)((ch & 1) * GSTAGE);
        const unsigned abase = st + a_off;
        const unsigned bbase = st + GBUF + b_off;

#pragma unroll
        for (int ks = 0; ks < 4; ks++) {
            const unsigned koff = (unsigned)(ks * 16 * 2);
            // B first (first MMA consumes bf[0])
            unsigned bf[4][2];
#pragma unroll
            for (int np = 0; np < 2; np++) {
                unsigned r0, r1, r2, r3;
                ldsm_x4(r0, r1, r2, r3,
                        bbase + koff + (unsigned)(np * 16 * GST * 2));
                bf[np * 2 + 0][0] = r0; bf[np * 2 + 0][1] = r2;
                bf[np * 2 + 1][0] = r1; bf[np * 2 + 1][1] = r3;
            }
            unsigned af[4][4];
#pragma unroll
            for (int mt = 0; mt < 4; mt++)
                ldsm_x4(af[mt][0], af[mt][1], af[mt][2], af[mt][3],
                        abase + koff + (unsigned)(mt * 16 * GST * 2));
#pragma unroll
            for (int mt = 0; mt < 4; mt++)
#pragma unroll
                for (int nt = 0; nt < 4; nt++)
                    mma16816h(acc[mt][nt], af[mt], bf[nt]);
        }
        __syncthreads();

        if (ch + 1 < NCH) {
            if (ch + 2 < NCH) {
                g_load(sbase, ch & 1, Xf, Wf, m0, n0, (ch + 2) * KC, tid);
                cpa_commit();
                cpa_wait<1>();
            } else {
                cpa_wait<0>();
            }
            __syncthreads();
        }
    }

    const int g   = lane >> 2;
    const int tig = lane & 3;
#pragma unroll
    for (int mt = 0; mt < 4; mt++) {
        const int r0 = m0 + wm * 64 + mt * 16 + g;
#pragma unroll
        for (int nt = 0; nt < 4; nt++) {
            const int cidx = n0 + wn * 32 + nt * 8 + tig * 2;
            const float2 bv = *(const float2*)(bias + cidx);
            const float x0 = acc[mt][nt][0] + bv.x;
            const float x1 = acc[mt][nt][1] + bv.y;
            const float x2 = acc[mt][nt][2] + bv.x;
            const float x3 = acc[mt][nt][3] + bv.y;
            if (Cf) {
                *(float2*)(Cf + (size_t)r0 * Dmodel + cidx) = make_float2(x0, x1);
                *(float2*)(Cf + (size_t)(r0 + 8) * Dmodel + cidx) = make_float2(x2, x3);
            } else {
                *(unsigned*)(C16 + (size_t)r0 * Dmodel + cidx) =
                    packf16(x0 * cscale, x1 * cscale);
                *(unsigned*)(C16 + (size_t)(r0 + 8) * Dmodel + cidx) =
                    packf16(x2 * cscale, x3 * cscale);
            }
        }
    }
}

__global__ __launch_bounds__(256, 2) void qkv_gemm(const float* __restrict__ bq,
                                                   const float* __restrict__ bk,
                                                   const float* __restrict__ bv)
{
    const int z = blockIdx.z;
    const float* bias = (z == 0) ? bq : (z == 1) ? bk : bv;
    const float cs = (z == 0) ? QSCALE : 1.0f;   // fold softmax scale AND log2(e) into Q
    gemm_body(g_xf + (size_t)z * NELEM, g_wf + (size_t)z * WELEM,
              bias, g_pf + (size_t)z * NELEM, nullptr, cs);
}

__global__ __launch_bounds__(256, 2) void out_gemm(const float* __restrict__ bo,
                                                   float* __restrict__ out)
{
    gemm_body(g_Cf, g_wf + (size_t)3 * WELEM, bo, nullptr, out, 1.0f);
}

// ---------------------------------------------------------------------------
// Flash attention, fp16 single-pass HMMA, cp.async 2-stage K/V pipeline.
// Software-pipelined ldsm->mma (2-deep frag ring); exp2-domain softmax.
// CTA: 128 q-rows x (b,h); 8 warps x 16 rows; j-tiles of 64.
// ---------------------------------------------------------------------------
#define FST 72
#define QBUF  (128 * FST * 2)     // 18432
#define KVBUF (64 * FST * 2)      // 9216
#define KVSTAGE (2 * KVBUF)       // 18432
#define FSMEM (QBUF + 2 * KVSTAGE)   // 55296

__device__ __forceinline__ void f_loadKV(unsigned kvbase, int stage, int jt,
                                         const __half* Kf, const __half* Vf, int tid)
{
    const int row = tid >> 2;
    const int c2  = tid & 3;
    const unsigned dst0 = kvbase + (unsigned)(stage * KVSTAGE + row * 144 + c2 * 32);
    const size_t src = (size_t)(jt + row) * Dmodel + c2 * 16;
    cpa16(dst0,              Kf + src);
    cpa16(dst0 + 16,         Kf + src + 8);
    cpa16(dst0 + KVBUF,      Vf + src);
    cpa16(dst0 + KVBUF + 16, Vf + src + 8);
}

__global__ __launch_bounds__(256, 2) void flash_attn()
{
    extern __shared__ __align__(16) char smf[];
    const unsigned sbase  = smem_u32(smf);
    const unsigned kvbase = sbase + QBUF;

    const int tid  = threadIdx.x;
    const int wid  = tid >> 5;
    const int lane = tid & 31;
    const int tg   = lane & 3;
    const int bh   = blockIdx.y;
    const int b    = bh >> 4;
    const int h    = bh & 15;
    const int q0   = blockIdx.x * 128;

    const size_t hoff = (size_t)b * Nseq * Dmodel + h * DKh;
    const __half* Qf = g_pf + hoff;
    const __half* Kf = g_pf + NELEM + hoff;
    const __half* Vf = g_pf + 2 * NELEM + hoff;

    // prologue
    {
        const int row = tid >> 1;
        const int c4  = tid & 1;
        const unsigned dq = sbase + (unsigned)(row * 144 + c4 * 64);
        const size_t src = (size_t)(q0 + row) * Dmodel + c4 * 32;
#pragma unroll
        for (int j = 0; j < 4; j++)
            cpa16(dq + j * 16, Qf + src + j * 8);
    }
    f_loadKV(kvbase, 0, 0, Kf, Vf, tid);
    cpa_commit();
    f_loadKV(kvbase, 1, 64, Kf, Vf, tid);
    cpa_commit();
    cpa_wait<1>();
    __syncthreads();

    // persistent Q fragments
    const unsigned qa = sbase +
        (unsigned)(((wid * 16 + (lane & 15)) * FST + (lane >> 4) * 8) * 2);
    unsigned aq[4][4];
#pragma unroll
    for (int ks = 0; ks < 4; ks++)
        ldsm_x4(aq[ks][0], aq[ks][1], aq[ks][2], aq[ks][3], qa + ks * 32);

    const unsigned kb_off = (unsigned)(((lane & 15) * FST + (lane >> 4) * 8) * 2);

    float oacc[8][4];
#pragma unroll
    for (int nt = 0; nt < 8; nt++)
#pragma unroll
        for (int i = 0; i < 4; i++) oacc[nt][i] = 0.0f;
    float mr0 = -1e30f, mr1 = -1e30f, lr0 = 0.0f, lr1 = 0.0f;

    const int NT = Nseq / 64;   // 32
    for (int jt = 0; jt < NT; jt++) {
        const unsigned st = kvbase + (unsigned)((jt & 1) * KVSTAGE);
        const unsigned kb = st + kb_off;
        const unsigned vb = st + KVBUF + kb_off;

        // ---- S = Q K^T (log2 domain; scale pre-folded into Q) ----
        float sacc[8][4];
#pragma unroll
        for (int nt = 0; nt < 8; nt++)
#pragma unroll
            for (int i = 0; i < 4; i++) sacc[nt][i] = 0.0f;

        {
            unsigned kf[2][4];
            ldsm_x4(kf[0][0], kf[0][1], kf[0][2], kf[0][3], kb);   // it=0: ks=0, jb=0
#pragma unroll
            for (int it = 0; it < 16; it++) {
                const int ks = it >> 2, jb = it & 3;
                if (it + 1 < 16) {
                    const int ks2 = (it + 1) >> 2, jb2 = (it + 1) & 3;
                    ldsm_x4(kf[(it + 1) & 1][0], kf[(it + 1) & 1][1],
                            kf[(it + 1) & 1][2], kf[(it + 1) & 1][3],
                            kb + (unsigned)((jb2 * 16 * FST + ks2 * 16) * 2));
                }
                unsigned bf0[2] = {kf[it & 1][0], kf[it & 1][2]};
                unsigned bf1[2] = {kf[it & 1][1], kf[it & 1][3]};
                mma16816h(sacc[jb * 2 + 0], aq[ks], bf0);
                mma16816h(sacc[jb * 2 + 1], aq[ks], bf1);
            }
        }

        // ---- online softmax (exp2 domain) ----
        float mx0 = -1e30f, mx1 = -1e30f;
#pragma unroll
        for (int nt = 0; nt < 8; nt++) {
            mx0 = fmaxf(mx0, fmaxf(sacc[nt][0], sacc[nt][1]));
            mx1 = fmaxf(mx1, fmaxf(sacc[nt][2], sacc[nt][3]));
        }
        mx0 = fmaxf(mx0, __shfl_xor_sync(0xffffffffu, mx0, 1));
        mx0 = fmaxf(mx0, __shfl_xor_sync(0xffffffffu, mx0, 2));
        mx1 = fmaxf(mx1, __shfl_xor_sync(0xffffffffu, mx1, 1));
        mx1 = fmaxf(mx1, __shfl_xor_sync(0xffffffffu, mx1, 2));
        const float mn0 = fmaxf(mr0, mx0);
        const float mn1 = fmaxf(mr1, mx1);
        const float al0 = exp2f(mr0 - mn0);
        const float al1 = exp2f(mr1 - mn1);

        unsigned pa[4][4];
        float rs0 = 0.0f, rs1 = 0.0f;
#pragma unroll
        for (int nt = 0; nt < 8; nt++) {
            const float p0 = exp2f(sacc[nt][0] - mn0);
            const float p1 = exp2f(sacc[nt][1] - mn0);
            const float p2 = exp2f(sacc[nt][2] - mn1);
            const float p3 = exp2f(sacc[nt][3] - mn1);
            rs0 += p0 + p1;
            rs1 += p2 + p3;
            const unsigned h01 = packf16(p0, p1);
            const unsigned h23 = packf16(p2, p3);
            const int t = nt >> 1;
            if ((nt & 1) == 0) { pa[t][0] = h01; pa[t][1] = h23; }
            else               { pa[t][2] = h01; pa[t][3] = h23; }
        }
        // rescale O only if some lane's max moved (al==1.0f exactly when unchanged)
        const bool nochg = (al0 == 1.0f) && (al1 == 1.0f);
        if (!__all_sync(0xffffffffu, nochg)) {
#pragma unroll
            for (int nt = 0; nt < 8; nt++) {
                oacc[nt][0] *= al0; oacc[nt][1] *= al0;
                oacc[nt][2] *= al1; oacc[nt][3] *= al1;
            }
        }
        rs0 += __shfl_xor_sync(0xffffffffu, rs0, 1);
        rs0 += __shfl_xor_sync(0xffffffffu, rs0, 2);
        rs1 += __shfl_xor_sync(0xffffffffu, rs1, 1);
        rs1 += __shfl_xor_sync(0xffffffffu, rs1, 2);
        lr0 = lr0 * al0 + rs0;
        lr1 = lr1 * al1 + rs1;
        mr0 = mn0; mr1 = mn1;

        // ---- O += P V (software-pipelined V-frag loads) ----
        {
            unsigned vf[2][4];
            ldsm_x4_t(vf[0][0], vf[0][1], vf[0][2], vf[0][3], vb);   // it=0: t=0, db=0
#pragma unroll
            for (int it = 0; it < 16; it++) {
                const int t = it >> 2, db = it & 3;
                if (it + 1 < 16) {
                    const int t2 = (it + 1) >> 2, db2 = (it + 1) & 3;
                    ldsm_x4_t(vf[(it + 1) & 1][0], vf[(it + 1) & 1][1],
                              vf[(it + 1) & 1][2], vf[(it + 1) & 1][3],
                              vb + (unsigned)((t2 * 16 * FST + db2 * 16) * 2));
                }
                unsigned b0[2] = {vf[it & 1][0], vf[it & 1][1]};
                unsigned b1[2] = {vf[it & 1][2], vf[it & 1][3]};
                mma16816h(oacc[db * 2 + 0], pa[t], b0);
                mma16816h(oacc[db * 2 + 1], pa[t], b1);
            }
        }

        __syncthreads();
        if (jt + 1 < NT) {
            if (jt + 2 < NT) {
                f_loadKV(kvbase, jt & 1, (jt + 2) * 64, Kf, Vf, tid);
                cpa_commit();
                cpa_wait<1>();
            } else {
                cpa_wait<0>();
            }
            __syncthreads();
        }
    }

    // ---- epilogue: write attention out as fp16 ----
    const float inv0 = 1.0f / lr0;
    const float inv1 = 1.0f / lr1;
    __half* Ch = g_Cf + hoff;
    const int row0 = q0 + wid * 16 + (lane >> 2);
#pragma unroll
    for (int nt = 0; nt < 8; nt++) {
        const int d = nt * 8 + tg * 2;
        *(unsigned*)(Ch + (size_t)row0 * Dmodel + d) =
            packf16(oacc[nt][0] * inv0, oacc[nt][1] * inv0);
        *(unsigned*)(Ch + (size_t)(row0 + 8) * Dmodel + d) =
            packf16(oacc[nt][2] * inv1, oacc[nt][3] * inv1);
    }
}

// ---------------------------------------------------------------------------
extern "C" void kernel_launch(void* const* d_in, const int* in_sizes, int n_in,
                              void* d_out, int out_size)
{
    const float* q  = (const float*)d_in[0];
    const float* k  = (const float*)d_in[1];
    const float* v  = (const float*)d_in[2];
    const float* Wq = (const float*)d_in[3];
    const float* bq = (const float*)d_in[4];
    const float* Wk = (const float*)d_in[5];
    const float* bk = (const float*)d_in[6];
    const float* Wv = (const float*)d_in[7];
    const float* bv = (const float*)d_in[8];
    const float* Wo = (const float*)d_in[9];
    const float* bo = (const float*)d_in[10];
    float* out = (float*)d_out;

    cudaFuncSetAttribute(flash_attn, cudaFuncAttributeMaxDynamicSharedMemorySize, FSMEM);
    cudaFuncSetAttribute(qkv_gemm, cudaFuncAttributeMaxDynamicSharedMemorySize, GSMEM);
    cudaFuncSetAttribute(out_gemm, cudaFuncAttributeMaxDynamicSharedMemorySize, GSMEM);

    conv_inputs<<<dim3(NELEM / 1024, 1, 3), 256>>>(q, k, v);
    conv_weights<<<dim3(WELEM / 1024, 1, 4), 256>>>(Wq, Wk, Wv, Wo);

    dim3 gqkv(Dmodel / 128, Mrows / 128, 3);   // 8 x 32 x 3
    qkv_gemm<<<gqkv, 256, GSMEM>>>(bq, bk, bv);

    dim3 gf(Nseq / 128, Bsz * Hh);             // 16 x 32
    flash_attn<<<gf, 256, FSMEM>>>();

    dim3 go(Dmodel / 128, Mrows / 128);        // 8 x 32
    out_gemm<<<go, 256, GSMEM>>>(bo, out);
}

// round 11
// speedup vs baseline: 5.6437x; 1.0136x over previous
#include <cuda_runtime.h>
#include <cuda_fp16.h>

// Problem constants
#define Bsz    2
#define Nseq   2048
#define Dmodel 1024
#define Hh     16
#define DKh    64
#define Mrows  4096
#define NELEM  (Mrows * Dmodel)     // 4,194,304
#define WELEM  (Dmodel * Dmodel)    // 1,048,576
#define SCALE  0.125f
#define QSCALE (0.125f * 1.44269504088896f)   // fold log2(e): softmax in exp2 domain

// ---- mma.sync / ldmatrix / cp.async helpers (base sm_80+ ISA) ----
__device__ __forceinline__ unsigned smem_u32(const void* p) {
    unsigned a;
    asm("{ .reg .u64 t; cvta.to.shared.u64 t, %1; cvt.u32.u64 %0, t; }" : "=r"(a) : "l"(p));
    return a;
}
__device__ __forceinline__ void ldsm_x4(unsigned& r0, unsigned& r1, unsigned& r2, unsigned& r3,
                                        unsigned addr) {
    asm volatile("ldmatrix.sync.aligned.m8n8.x4.shared.b16 {%0,%1,%2,%3}, [%4];"
                 : "=r"(r0), "=r"(r1), "=r"(r2), "=r"(r3) : "r"(addr));
}
__device__ __forceinline__ void ldsm_x4_t(unsigned& r0, unsigned& r1, unsigned& r2, unsigned& r3,
                                          unsigned addr) {
    asm volatile("ldmatrix.sync.aligned.m8n8.x4.trans.shared.b16 {%0,%1,%2,%3}, [%4];"
                 : "=r"(r0), "=r"(r1), "=r"(r2), "=r"(r3) : "r"(addr));
}
__device__ __forceinline__ void mma16816h(float* c, const unsigned* a, const unsigned* b) {
    asm volatile("mma.sync.aligned.m16n8k16.row.col.f32.f16.f16.f32 "
                 "{%0,%1,%2,%3},{%4,%5,%6,%7},{%8,%9},{%0,%1,%2,%3};"
                 : "+f"(c[0]), "+f"(c[1]), "+f"(c[2]), "+f"(c[3])
                 : "r"(a[0]), "r"(a[1]), "r"(a[2]), "r"(a[3]), "r"(b[0]), "r"(b[1]));
}
__device__ __forceinline__ void cpa16(unsigned dst, const void* src) {
    asm volatile("cp.async.cg.shared.global [%0], [%1], 16;" :: "r"(dst), "l"(src));
}
__device__ __forceinline__ void cpa_commit() { asm volatile("cp.async.commit_group;"); }
template<int N> __device__ __forceinline__ void cpa_wait() {
    asm volatile("cp.async.wait_group %0;" :: "n"(N));
}
__device__ __forceinline__ unsigned packf16(float x, float y) {
    __half2 t = __floats2half2_rn(x, y);
    return *reinterpret_cast<unsigned*>(&t);
}
__device__ __forceinline__ unsigned ex2h2(unsigned d) {
    unsigned e;
    asm("ex2.approx.f16x2 %0, %1;" : "=r"(e) : "r"(d));
    return e;
}

// ---- scratch (fp16) ----
__device__ __half g_xf[3 * NELEM];   // converted inputs q,k,v
__device__ __half g_wf[4 * WELEM];   // converted weights Wq,Wk,Wv,Wo
__device__ __half g_pf[3 * NELEM];   // projected Q(pre-scaled),K,V
__device__ __half g_Cf[NELEM];       // attention output

// ---------------------------------------------------------------------------
// Convert kernels: fp32 -> fp16
// ---------------------------------------------------------------------------
__global__ __launch_bounds__(256) void conv_inputs(const float* __restrict__ q,
                                                   const float* __restrict__ k,
                                                   const float* __restrict__ v)
{
    const int z = blockIdx.z;
    const float* src = (z == 0) ? q : (z == 1) ? k : v;
    __half* dst = g_xf + (size_t)z * NELEM;
    const size_t i = ((size_t)blockIdx.x * 256 + threadIdx.x) * 4;
    float4 f = *(const float4*)(src + i);
    uint2 o;
    o.x = packf16(f.x, f.y);
    o.y = packf16(f.z, f.w);
    *(uint2*)(dst + i) = o;
}

__global__ __launch_bounds__(256) void conv_weights(const float* __restrict__ wq,
                                                    const float* __restrict__ wk,
                                                    const float* __restrict__ wv,
                                                    const float* __restrict__ wo)
{
    const int z = blockIdx.z;
    const float* src = (z == 0) ? wq : (z == 1) ? wk : (z == 2) ? wv : wo;
    __half* dst = g_wf + (size_t)z * WELEM;
    const size_t i = ((size_t)blockIdx.x * 256 + threadIdx.x) * 4;
    float4 f = *(const float4*)(src + i);
    uint2 o;
    o.x = packf16(f.x, f.y);
    o.y = packf16(f.z, f.w);
    *(uint2*)(dst + i) = o;
}

// ---------------------------------------------------------------------------
// fp16 single-pass HMMA GEMM, cp.async 2-stage: C = X @ W^T + bias
// Tile 128x128, Kc=64, 8 warps (2x4), warp tile 64x32.
// ---------------------------------------------------------------------------
#define KC 64
#define NCH (Dmodel / KC)     // 16
#define GST 72
#define GBUF (128 * GST * 2)  // 18432 B
#define GSTAGE (2 * GBUF)     // 36864 B
#define GSMEM (2 * GSTAGE)    // 73728 B

__device__ __forceinline__ void g_load(unsigned sbase, int stage,
                                       const __half* Xf, const __half* Wf,
                                       int m0, int n0, int k0, int tid)
{
    const int row = tid >> 1;
    const int co  = (tid & 1) * 32;
    const unsigned dst0 = sbase + (unsigned)(stage * GSTAGE + row * 144 + (tid & 1) * 64);
    const size_t asrc = (size_t)(m0 + row) * Dmodel + k0 + co;
    const size_t bsrc = (size_t)(n0 + row) * Dmodel + k0 + co;
#pragma unroll
    for (int j = 0; j < 4; j++) {
        cpa16(dst0 + j * 16,        Xf + asrc + j * 8);
        cpa16(dst0 + GBUF + j * 16, Wf + bsrc + j * 8);
    }
}

__device__ __forceinline__ void gemm_body(const __half* __restrict__ Xf,
                                          const __half* __restrict__ Wf,
                                          const float* __restrict__ bias,
                                          __half* C16, float* Cf, float cscale)
{
    extern __shared__ __align__(16) char smg[];
    const unsigned sbase = smem_u32(smg);

    const int tid  = threadIdx.x;
    const int wid  = tid >> 5;
    const int lane = tid & 31;
    const int wm   = wid >> 2;
    const int wn   = wid & 3;
    const int m0   = blockIdx.y * 128;
    const int n0   = blockIdx.x * 128;

    float acc[4][4][4];
#pragma unroll
    for (int mt = 0; mt < 4; mt++)
#pragma unroll
        for (int nt = 0; nt < 4; nt++)
#pragma unroll
            for (int i = 0; i < 4; i++) acc[mt][nt][i] = 0.0f;

    const unsigned a_off = (unsigned)(((wm * 64 + (lane & 15)) * GST + (lane >> 4) * 8) * 2);
    const unsigned b_off = (unsigned)(((wn * 32 + (lane & 15)) * GST + (lane >> 4) * 8) * 2);

    g_load(sbase, 0, Xf, Wf, m0, n0, 0, tid);
    cpa_commit();
    g_load(sbase, 1, Xf, Wf, m0, n0, KC, tid);
    cpa_commit();
    cpa_wait<1>();
    __syncthreads();

    for (int ch = 0; ch < NCH; ch++) {
        const unsigned st = sbase + (unsigned)((ch & 1) * GSTAGE);
        const unsigned abase = st + a_off;
        const unsigned bbase = st + GBUF + b_off;

#pragma unroll
        for (int ks = 0; ks < 4; ks++) {
            const unsigned koff = (unsigned)(ks * 16 * 2);
            unsigned bf[4][2];
#pragma unroll
            for (int np = 0; np < 2; np++) {
                unsigned r0, r1, r2, r3;
                ldsm_x4(r0, r1, r2, r3,
                        bbase + koff + (unsigned)(np * 16 * GST * 2));
                bf[np * 2 + 0][0] = r0; bf[np * 2 + 0][1] = r2;
                bf[np * 2 + 1][0] = r1; bf[np * 2 + 1][1] = r3;
            }
            unsigned af[4][4];
#pragma unroll
            for (int mt = 0; mt < 4; mt++)
                ldsm_x4(af[mt][0], af[mt][1], af[mt][2], af[mt][3],
                        abase + koff + (unsigned)(mt * 16 * GST * 2));
#pragma unroll
            for (int mt = 0; mt < 4; mt++)
#pragma unroll
                for (int nt = 0; nt < 4; nt++)
                    mma16816h(acc[mt][nt], af[mt], bf[nt]);
        }
        __syncthreads();

        if (ch + 1 < NCH) {
            if (ch + 2 < NCH) {
                g_load(sbase, ch & 1, Xf, Wf, m0, n0, (ch + 2) * KC, tid);
                cpa_commit();
                cpa_wait<1>();
            } else {
                cpa_wait<0>();
            }
            __syncthreads();
        }
    }

    const int g   = lane >> 2;
    const int tig = lane & 3;
#pragma unroll
    for (int mt = 0; mt < 4; mt++) {
        const int r0 = m0 + wm * 64 + mt * 16 + g;
#pragma unroll
        for (int nt = 0; nt < 4; nt++) {
            const int cidx = n0 + wn * 32 + nt * 8 + tig * 2;
            const float2 bv = *(const float2*)(bias + cidx);
            const float x0 = acc[mt][nt][0] + bv.x;
            const float x1 = acc[mt][nt][1] + bv.y;
            const float x2 = acc[mt][nt][2] + bv.x;
            const float x3 = acc[mt][nt][3] + bv.y;
            if (Cf) {
                *(float2*)(Cf + (size_t)r0 * Dmodel + cidx) = make_float2(x0, x1);
                *(float2*)(Cf + (size_t)(r0 + 8) * Dmodel + cidx) = make_float2(x2, x3);
            } else {
                *(unsigned*)(C16 + (size_t)r0 * Dmodel + cidx) =
                    packf16(x0 * cscale, x1 * cscale);
                *(unsigned*)(C16 + (size_t)(r0 + 8) * Dmodel + cidx) =
                    packf16(x2 * cscale, x3 * cscale);
            }
        }
    }
}

__global__ __launch_bounds__(256, 2) void qkv_gemm(const float* __restrict__ bq,
                                                   const float* __restrict__ bk,
                                                   const float* __restrict__ bv)
{
    const int z = blockIdx.z;
    const float* bias = (z == 0) ? bq : (z == 1) ? bk : bv;
    const float cs = (z == 0) ? QSCALE : 1.0f;
    gemm_body(g_xf + (size_t)z * NELEM, g_wf + (size_t)z * WELEM,
              bias, g_pf + (size_t)z * NELEM, nullptr, cs);
}

__global__ __launch_bounds__(256, 2) void out_gemm(const float* __restrict__ bo,
                                                   float* __restrict__ out)
{
    gemm_body(g_Cf, g_wf + (size_t)3 * WELEM, bo, nullptr, out, 1.0f);
}

// ---------------------------------------------------------------------------
// Flash attention, fp16 HMMA, cp.async 2-stage K/V pipeline.
// half2 softmax: ex2.approx.f16x2 produces PV fragments directly.
// CTA: 128 q-rows x (b,h); 8 warps x 16 rows; j-tiles of 64.
// ---------------------------------------------------------------------------
#define FST 72
#define QBUF  (128 * FST * 2)     // 18432
#define KVBUF (64 * FST * 2)      // 9216
#define KVSTAGE (2 * KVBUF)       // 18432
#define FSMEM (QBUF + 2 * KVSTAGE)   // 55296

__device__ __forceinline__ void f_loadKV(unsigned kvbase, int stage, int jt,
                                         const __half* Kf, const __half* Vf, int tid)
{
    const int row = tid >> 2;
    const int c2  = tid & 3;
    const unsigned dst0 = kvbase + (unsigned)(stage * KVSTAGE + row * 144 + c2 * 32);
    const size_t src = (size_t)(jt + row) * Dmodel + c2 * 16;
    cpa16(dst0,              Kf + src);
    cpa16(dst0 + 16,         Kf + src + 8);
    cpa16(dst0 + KVBUF,      Vf + src);
    cpa16(dst0 + KVBUF + 16, Vf + src + 8);
}

__global__ __launch_bounds__(256, 2) void flash_attn()
{
    extern __shared__ __align__(16) char smf[];
    const unsigned sbase  = smem_u32(smf);
    const unsigned kvbase = sbase + QBUF;

    const int tid  = threadIdx.x;
    const int wid  = tid >> 5;
    const int lane = tid & 31;
    const int tg   = lane & 3;
    const int bh   = blockIdx.y;
    const int b    = bh >> 4;
    const int h    = bh & 15;
    const int q0   = blockIdx.x * 128;

    const size_t hoff = (size_t)b * Nseq * Dmodel + h * DKh;
    const __half* Qf = g_pf + hoff;
    const __half* Kf = g_pf + NELEM + hoff;
    const __half* Vf = g_pf + 2 * NELEM + hoff;

    // prologue
    {
        const int row = tid >> 1;
        const int c4  = tid & 1;
        const unsigned dq = sbase + (unsigned)(row * 144 + c4 * 64);
        const size_t src = (size_t)(q0 + row) * Dmodel + c4 * 32;
#pragma unroll
        for (int j = 0; j < 4; j++)
            cpa16(dq + j * 16, Qf + src + j * 8);
    }
    f_loadKV(kvbase, 0, 0, Kf, Vf, tid);
    cpa_commit();
    f_loadKV(kvbase, 1, 64, Kf, Vf, tid);
    cpa_commit();
    cpa_wait<1>();
    __syncthreads();

    // persistent Q fragments
    const unsigned qa = sbase +
        (unsigned)(((wid * 16 + (lane & 15)) * FST + (lane >> 4) * 8) * 2);
    unsigned aq[4][4];
#pragma unroll
    for (int ks = 0; ks < 4; ks++)
        ldsm_x4(aq[ks][0], aq[ks][1], aq[ks][2], aq[ks][3], qa + ks * 32);

    const unsigned kb_off = (unsigned)(((lane & 15) * FST + (lane >> 4) * 8) * 2);

    float oacc[8][4];
#pragma unroll
    for (int nt = 0; nt < 8; nt++)
#pragma unroll
        for (int i = 0; i < 4; i++) oacc[nt][i] = 0.0f;
    float mr0 = -1e30f, mr1 = -1e30f, lr0 = 0.0f, lr1 = 0.0f;

    const int NT = Nseq / 64;   // 32
    for (int jt = 0; jt < NT; jt++) {
        const unsigned st = kvbase + (unsigned)((jt & 1) * KVSTAGE);
        const unsigned kb = st + kb_off;
        const unsigned vb = st + KVBUF + kb_off;

        // ---- S = Q K^T (log2 domain; scale pre-folded into Q) ----
        float sacc[8][4];
#pragma unroll
        for (int nt = 0; nt < 8; nt++)
#pragma unroll
            for (int i = 0; i < 4; i++) sacc[nt][i] = 0.0f;

        {
            unsigned kf[2][4];
            ldsm_x4(kf[0][0], kf[0][1], kf[0][2], kf[0][3], kb);
#pragma unroll
            for (int it = 0; it < 16; it++) {
                const int ks = it >> 2, jb = it & 3;
                if (it + 1 < 16) {
                    const int ks2 = (it + 1) >> 2, jb2 = (it + 1) & 3;
                    ldsm_x4(kf[(it + 1) & 1][0], kf[(it + 1) & 1][1],
                            kf[(it + 1) & 1][2], kf[(it + 1) & 1][3],
                            kb + (unsigned)((jb2 * 16 * FST + ks2 * 16) * 2));
                }
                unsigned bf0[2] = {kf[it & 1][0], kf[it & 1][2]};
                unsigned bf1[2] = {kf[it & 1][1], kf[it & 1][3]};
                mma16816h(sacc[jb * 2 + 0], aq[ks], bf0);
                mma16816h(sacc[jb * 2 + 1], aq[ks], bf1);
            }
        }

        // ---- online softmax (half2 exp; ex2 output IS the PV fragment) ----
        float mx0 = -1e30f, mx1 = -1e30f;
#pragma unroll
        for (int nt = 0; nt < 8; nt++) {
            mx0 = fmaxf(mx0, fmaxf(sacc[nt][0], sacc[nt][1]));
            mx1 = fmaxf(mx1, fmaxf(sacc[nt][2], sacc[nt][3]));
        }
        mx0 = fmaxf(mx0, __shfl_xor_sync(0xffffffffu, mx0, 1));
        mx0 = fmaxf(mx0, __shfl_xor_sync(0xffffffffu, mx0, 2));
        mx1 = fmaxf(mx1, __shfl_xor_sync(0xffffffffu, mx1, 1));
        mx1 = fmaxf(mx1, __shfl_xor_sync(0xffffffffu, mx1, 2));
        const float mn0 = fmaxf(mr0, mx0);
        const float mn1 = fmaxf(mr1, mx1);
        const float al0 = exp2f(mr0 - mn0);
        const float al1 = exp2f(mr1 - mn1);

        unsigned pa[4][4];
        float rs0 = 0.0f, rs1 = 0.0f;
#pragma unroll
        for (int grp = 0; grp < 2; grp++) {
            __half2 a01 = __float2half2_rn(0.0f);
            __half2 a23 = __float2half2_rn(0.0f);
#pragma unroll
            for (int k2 = 0; k2 < 4; k2++) {
                const int nt = grp * 4 + k2;
                const unsigned e01 = ex2h2(packf16(sacc[nt][0] - mn0, sacc[nt][1] - mn0));
                const unsigned e23 = ex2h2(packf16(sacc[nt][2] - mn1, sacc[nt][3] - mn1));
                const int t = nt >> 1;
                if ((nt & 1) == 0) { pa[t][0] = e01; pa[t][1] = e23; }
                else               { pa[t][2] = e01; pa[t][3] = e23; }
                a01 = __hadd2(a01, *reinterpret_cast<const __half2*>(&e01));
                a23 = __hadd2(a23, *reinterpret_cast<const __half2*>(&e23));
            }
            const float2 f01 = __half22float2(a01);
            const float2 f23 = __half22float2(a23);
            rs0 += f01.x + f01.y;
            rs1 += f23.x + f23.y;
        }
        // rescale O only if some lane's max moved
        const bool nochg = (al0 == 1.0f) && (al1 == 1.0f);
        if (!__all_sync(0xffffffffu, nochg)) {
#pragma unroll
            for (int nt = 0; nt < 8; nt++) {
                oacc[nt][0] *= al0; oacc[nt][1] *= al0;
                oacc[nt][2] *= al1; oacc[nt][3] *= al1;
            }
        }
        rs0 += __shfl_xor_sync(0xffffffffu, rs0, 1);
        rs0 += __shfl_xor_sync(0xffffffffu, rs0, 2);
        rs1 += __shfl_xor_sync(0xffffffffu, rs1, 1);
        rs1 += __shfl_xor_sync(0xffffffffu, rs1, 2);
        lr0 = lr0 * al0 + rs0;
        lr1 = lr1 * al1 + rs1;
        mr0 = mn0; mr1 = mn1;

        // ---- O += P V (software-pipelined V-frag loads) ----
        {
            unsigned vf[2][4];
            ldsm_x4_t(vf[0][0], vf[0][1], vf[0][2], vf[0][3], vb);
#pragma unroll
            for (int it = 0; it < 16; it++) {
                const int t = it >> 2, db = it & 3;
                if (it + 1 < 16) {
                    const int t2 = (it + 1) >> 2, db2 = (it + 1) & 3;
                    ldsm_x4_t(vf[(it + 1) & 1][0], vf[(it + 1) & 1][1],
                              vf[(it + 1) & 1][2], vf[(it + 1) & 1][3],
                              vb + (unsigned)((t2 * 16 * FST + db2 * 16) * 2));
                }
                unsigned b0[2] = {vf[it & 1][0], vf[it & 1][1]};
                unsigned b1[2] = {vf[it & 1][2], vf[it & 1][3]};
                mma16816h(oacc[db * 2 + 0], pa[t], b0);
                mma16816h(oacc[db * 2 + 1], pa[t], b1);
            }
        }

        __syncthreads();
        if (jt + 1 < NT) {
            if (jt + 2 < NT) {
                f_loadKV(kvbase, jt & 1, (jt + 2) * 64, Kf, Vf, tid);
                cpa_commit();
                cpa_wait<1>();
            } else {
                cpa_wait<0>();
            }
            __syncthreads();
        }
    }

    // ---- epilogue: write attention out as fp16 ----
    const float inv0 = 1.0f / lr0;
    const float inv1 = 1.0f / lr1;
    __half* Ch = g_Cf + hoff;
    const int row0 = q0 + wid * 16 + (lane >> 2);
#pragma unroll
    for (int nt = 0; nt < 8; nt++) {
        const int d = nt * 8 + tg * 2;
        *(unsigned*)(Ch + (size_t)row0 * Dmodel + d) =
            packf16(oacc[nt][0] * inv0, oacc[nt][1] * inv0);
        *(unsigned*)(Ch + (size_t)(row0 + 8) * Dmodel + d) =
            packf16(oacc[nt][2] * inv1, oacc[nt][3] * inv1);
    }
}

// ---------------------------------------------------------------------------
extern "C" void kernel_launch(void* const* d_in, const int* in_sizes, int n_in,
                              void* d_out, int out_size)
{
    const float* q  = (const float*)d_in[0];
    const float* k  = (const float*)d_in[1];
    const float* v  = (const float*)d_in[2];
    const float* Wq = (const float*)d_in[3];
    const float* bq = (const float*)d_in[4];
    const float* Wk = (const float*)d_in[5];
    const float* bk = (const float*)d_in[6];
    const float* Wv = (const float*)d_in[7];
    const float* bv = (const float*)d_in[8];
    const float* Wo = (const float*)d_in[9];
    const float* bo = (const float*)d_in[10];
    float* out = (float*)d_out;

    cudaFuncSetAttribute(flash_attn, cudaFuncAttributeMaxDynamicSharedMemorySize, FSMEM);
    cudaFuncSetAttribute(qkv_gemm, cudaFuncAttributeMaxDynamicSharedMemorySize, GSMEM);
    cudaFuncSetAttribute(out_gemm, cudaFuncAttributeMaxDynamicSharedMemorySize, GSMEM);

    conv_inputs<<<dim3(NELEM / 1024, 1, 3), 256>>>(q, k, v);
    conv_weights<<<dim3(WELEM / 1024, 1, 4), 256>>>(Wq, Wk, Wv, Wo);

    dim3 gqkv(Dmodel / 128, Mrows / 128, 3);   // 8 x 32 x 3
    qkv_gemm<<<gqkv, 256, GSMEM>>>(bq, bk, bv);

    dim3 gf(Nseq / 128, Bsz * Hh);             // 16 x 32
    flash_attn<<<gf, 256, FSMEM>>>();

    dim3 go(Dmodel / 128, Mrows / 128);        // 8 x 32
    out_gemm<<<go, 256, GSMEM>>>(bo, out);
}